// round 2
// baseline (speedup 1.0000x reference)
#include <cuda_runtime.h>

#define BSZ 8
#define SEQ 8192
#define DIM 128
#define NTOK (BSZ*SEQ)
#define MT 64
#define CHUNK 128
#define NCH (SEQ/CHUNK)

// ---------------- scratch (static device allocations only) ----------------
__device__ float d_at[NTOK*DIM];
__device__ float d_bt[NTOK*DIM];
__device__ float d_hf[NTOK*DIM];
__device__ float d_hb[NTOK*DIM];
__device__ float d_x2[NTOK*DIM];
__device__ float d_cAf[BSZ*NCH*DIM], d_cHf[BSZ*NCH*DIM];
__device__ float d_cAb[BSZ*NCH*DIM], d_cHb[BSZ*NCH*DIM];
__device__ float d_inf[BSZ*NCH*DIM], d_inb[BSZ*NCH*DIM];
__device__ float d_scal[BSZ*6];   // per batch: s1,b1,g1,s2,b2,g2
__device__ float d_loga[DIM];

// ---------------- helpers ----------------
__device__ __forceinline__ float warp_sum(float v) {
#pragma unroll
    for (int o = 16; o; o >>= 1) v += __shfl_xor_sync(0xffffffffu, v, o);
    return v;
}

__device__ __forceinline__ float sigm(float v) { return 1.f / (1.f + expf(-v)); }

// load a 128x128 fp32 weight block (row-major, contiguous) into smem
__device__ __forceinline__ void load_w(float* W_s, const float* __restrict__ g, int tid) {
    const float4* g4 = (const float4*)g;
    float4* s4 = (float4*)W_s;
#pragma unroll 4
    for (int i = tid; i < 128 * 32; i += 256) s4[i] = g4[i];
}

// C(64x128) += A(64x128) * W(128x128). Thread computes 4 rows x 8 cols.
__device__ __forceinline__ void gemm_tile(const float* __restrict__ A_s,
                                          const float* __restrict__ W_s,
                                          float acc[4][8], int r0, int c0) {
#pragma unroll 4
    for (int k = 0; k < 128; k++) {
        float4 bl = *(const float4*)(W_s + k * 128 + c0);
        float4 bh = *(const float4*)(W_s + k * 128 + c0 + 4);
        float bv[8] = {bl.x, bl.y, bl.z, bl.w, bh.x, bh.y, bh.z, bh.w};
        float av[4];
#pragma unroll
        for (int i = 0; i < 4; i++) av[i] = A_s[(r0 + i) * 128 + k];
#pragma unroll
        for (int i = 0; i < 4; i++)
#pragma unroll
            for (int j = 0; j < 8; j++) acc[i][j] = fmaf(av[i], bv[j], acc[i][j]);
    }
}

// ---------------- K0: per-batch conditioning scalars + log(a) ----------------
__global__ void k0(const float* __restrict__ c,
                   const float* w0, const float* b0, const float* w1, const float* b1,
                   const float* w2, const float* b2, const float* w3, const float* b3,
                   const float* w4, const float* b4, const float* w5, const float* b5,
                   const float* __restrict__ rnn_a) {
    const float* ws[6] = {w0, w1, w2, w3, w4, w5};
    const float* bs[6] = {b0, b1, b2, b3, b4, b5};
    int tid = threadIdx.x, lane = tid & 31, wp = tid >> 5;
    for (int idx = wp; idx < 48; idx += 8) {
        int b = idx / 6, j = idx % 6;
        float s = 0.f;
        for (int k = lane; k < 128; k += 32) s += c[b * 128 + k] * ws[j][k];
        s = warp_sum(s);
        if (lane == 0) d_scal[b * 6 + j] = s + bs[j][0];
    }
    if (tid < 128) d_loga[tid] = logf(rnn_a[tid]);
}

// ---------------- K1: LN -> cond -> LN -> u -> gates -> at/bt ----------------
__global__ __launch_bounds__(256) void k1(const float* __restrict__ x,
                                          const float* __restrict__ win, const float* __restrict__ bin,
                                          const float* __restrict__ pos,
                                          const float* __restrict__ wi, const float* __restrict__ bi,
                                          const float* __restrict__ wr, const float* __restrict__ br) {
    extern __shared__ float sm[];
    float* A_s = sm;                  // 64x128  (lnh)
    float* U_s = sm + MT * 128;       // 64x128  (u)
    float* W_s = sm + 2 * MT * 128;   // 128x128
    int tid = threadIdx.x, lane = tid & 31, wp = tid >> 5;
    int t0 = blockIdx.x * MT;
    int b = t0 / SEQ, l0 = t0 % SEQ;
    float s1 = d_scal[b * 6 + 0], bc1 = d_scal[b * 6 + 1];
    float alpha = 1.f + s1;
    (void)bc1; // bc1 shifts h uniformly; second LN removes the shift (mean(lnx)=0)

    // LayerNorm(x), then analytic LayerNorm of h = alpha*lnx + bc1
#pragma unroll
    for (int rep = 0; rep < MT / 8; rep++) {
        int r = wp * (MT / 8) + rep;
        float4 v = ((const float4*)(x + (size_t)(t0 + r) * DIM))[lane];
        float s = v.x + v.y + v.z + v.w;
        float sq = v.x * v.x + v.y * v.y + v.z * v.z + v.w * v.w;
        s = warp_sum(s); sq = warp_sum(sq);
        float m = s * (1.f / 128.f);
        float var = sq * (1.f / 128.f) - m * m;
        float r1 = rsqrtf(var + 1e-6f);
        float varln = var * r1 * r1;                        // var/(var+eps)
        float sc = alpha * rsqrtf(alpha * alpha * varln + 1e-6f) * r1;
        float4 o;
        o.x = (v.x - m) * sc; o.y = (v.y - m) * sc;
        o.z = (v.z - m) * sc; o.w = (v.w - m) * sc;
        ((float4*)(A_s + r * 128))[lane] = o;
    }
    __syncthreads();
    load_w(W_s, win, tid);
    __syncthreads();

    int ty = tid / 16, tx = tid % 16, r0 = ty * 4, c0 = tx * 8;
    float acc[4][8];
#pragma unroll
    for (int i = 0; i < 4; i++)
#pragma unroll
        for (int j = 0; j < 8; j++) acc[i][j] = 0.f;
    gemm_tile(A_s, W_s, acc, r0, c0);

    // u = acc + bias + pos_emb
#pragma unroll
    for (int i = 0; i < 4; i++) {
        int row = r0 + i, l = l0 + row;
#pragma unroll
        for (int j = 0; j < 8; j++) {
            int col = c0 + j;
            U_s[row * 128 + col] = acc[i][j] + bin[col] + pos[(size_t)l * DIM + col];
        }
    }
    __syncthreads();
    load_w(W_s, wi, tid);
    __syncthreads();

    float acc2[4][8];
#pragma unroll
    for (int i = 0; i < 4; i++)
#pragma unroll
        for (int j = 0; j < 8; j++) acc2[i][j] = 0.f;
    gemm_tile(U_s, W_s, acc2, r0, c0);
    float giv[4][8];
#pragma unroll
    for (int i = 0; i < 4; i++)
#pragma unroll
        for (int j = 0; j < 8; j++) giv[i][j] = sigm(acc2[i][j] + bi[c0 + j]);
    __syncthreads();
    load_w(W_s, wr, tid);
    __syncthreads();

#pragma unroll
    for (int i = 0; i < 4; i++)
#pragma unroll
        for (int j = 0; j < 8; j++) acc2[i][j] = 0.f;
    gemm_tile(U_s, W_s, acc2, r0, c0);

#pragma unroll
    for (int i = 0; i < 4; i++) {
        int row = r0 + i;
#pragma unroll
        for (int j = 0; j < 8; j++) {
            int col = c0 + j;
            float gr = sigm(acc2[i][j] + br[col]);
            float at = expf(8.f * gr * d_loga[col]);
            float u = U_s[row * 128 + col];
            float bt = sqrtf(fmaxf(1.f - at * at, 0.f)) * giv[i][j] * u;
            size_t gi = (size_t)(t0 + row) * DIM + col;
            d_at[gi] = at;
            d_bt[gi] = bt;
        }
    }
}

// ---------------- K2: per-chunk scan carries (fwd + bwd) ----------------
__global__ __launch_bounds__(128) void k2() {
    int b = blockIdx.x / NCH, ch = blockIdx.x % NCH, h = threadIdx.x;
    size_t base = ((size_t)b * SEQ + (size_t)ch * CHUNK) * DIM + h;
    float Af = 1.f, Hf = 0.f;
    for (int i = 0; i < CHUNK; i++) {
        float a = d_at[base + (size_t)i * DIM], bb = d_bt[base + (size_t)i * DIM];
        Hf = fmaf(a, Hf, bb); Af *= a;
    }
    float Ab = 1.f, Hb = 0.f;
    for (int i = CHUNK - 1; i >= 0; i--) {
        float a = d_at[base + (size_t)i * DIM], bb = d_bt[base + (size_t)i * DIM];
        Hb = fmaf(a, Hb, bb); Ab *= a;
    }
    int ci = (b * NCH + ch) * DIM + h;
    d_cAf[ci] = Af; d_cHf[ci] = Hf; d_cAb[ci] = Ab; d_cHb[ci] = Hb;
}

// ---------------- K3: combine carries across chunks ----------------
__global__ __launch_bounds__(128) void k3() {
    int b = blockIdx.x, h = threadIdx.x;
    float p = 0.f;
    for (int ch = 0; ch < NCH; ch++) {
        int ci = (b * NCH + ch) * DIM + h;
        d_inf[ci] = p;
        p = fmaf(d_cAf[ci], p, d_cHf[ci]);
    }
    p = 0.f;
    for (int ch = NCH - 1; ch >= 0; ch--) {
        int ci = (b * NCH + ch) * DIM + h;
        d_inb[ci] = p;
        p = fmaf(d_cAb[ci], p, d_cHb[ci]);
    }
}

// ---------------- K4: apply scans with correct init, write hf/hb ----------------
__global__ __launch_bounds__(128) void k4() {
    int b = blockIdx.x / NCH, ch = blockIdx.x % NCH, h = threadIdx.x;
    size_t base = ((size_t)b * SEQ + (size_t)ch * CHUNK) * DIM + h;
    int ci = (b * NCH + ch) * DIM + h;
    float hf = d_inf[ci];
    for (int i = 0; i < CHUNK; i++) {
        size_t idx = base + (size_t)i * DIM;
        hf = fmaf(d_at[idx], hf, d_bt[idx]);
        d_hf[idx] = hf;
    }
    float hb = d_inb[ci];
    for (int i = CHUNK - 1; i >= 0; i--) {
        size_t idx = base + (size_t)i * DIM;
        hb = fmaf(d_at[idx], hb, d_bt[idx]);
        d_hb[idx] = hb;
    }
}

// ---------------- K5: r = [hf|hb] @ Wout + b ; x2 = x + g1*r ----------------
__global__ __launch_bounds__(256) void k5(const float* __restrict__ x,
                                          const float* __restrict__ wout,
                                          const float* __restrict__ bout) {
    extern __shared__ float sm[];
    float* A_s = sm;                // 64x128
    float* W_s = sm + MT * 128;     // 128x128
    int tid = threadIdx.x;
    int t0 = blockIdx.x * MT;
    int b = t0 / SEQ;
    float g1 = d_scal[b * 6 + 2];
    int ty = tid / 16, tx = tid % 16, r0 = ty * 4, c0 = tx * 8;
    float acc[4][8];
#pragma unroll
    for (int i = 0; i < 4; i++)
#pragma unroll
        for (int j = 0; j < 8; j++) acc[i][j] = 0.f;

    // pass 1: hf x Wout[0:128]
    {
        const float4* src = (const float4*)(d_hf + (size_t)t0 * DIM);
        float4* dst = (float4*)A_s;
        for (int i = tid; i < MT * 32; i += 256) dst[i] = src[i];
    }
    load_w(W_s, wout, tid);
    __syncthreads();
    gemm_tile(A_s, W_s, acc, r0, c0);
    __syncthreads();
    // pass 2: hb x Wout[128:256]
    {
        const float4* src = (const float4*)(d_hb + (size_t)t0 * DIM);
        float4* dst = (float4*)A_s;
        for (int i = tid; i < MT * 32; i += 256) dst[i] = src[i];
    }
    load_w(W_s, wout + 128 * 128, tid);
    __syncthreads();
    gemm_tile(A_s, W_s, acc, r0, c0);

#pragma unroll
    for (int i = 0; i < 4; i++) {
        int row = r0 + i;
#pragma unroll
        for (int j = 0; j < 8; j++) {
            int col = c0 + j;
            float r = acc[i][j] + bout[col];
            size_t gi = (size_t)(t0 + row) * DIM + col;
            d_x2[gi] = x[gi] + g1 * r;
        }
    }
}

// ---------------- K6: LN -> cond -> gelu MLP -> out = x2 + g2*m ----------------
__global__ __launch_bounds__(256) void k6(const float* __restrict__ w1, const float* __restrict__ b1p,
                                          const float* __restrict__ w2, const float* __restrict__ b2p,
                                          float* __restrict__ out) {
    extern __shared__ float sm[];
    float* A_s = sm;                  // 64x128 (h2)
    float* G_s = sm + MT * 128;       // 64x128 (gelu act)
    float* W_s = sm + 2 * MT * 128;   // 128x128
    int tid = threadIdx.x, lane = tid & 31, wp = tid >> 5;
    int t0 = blockIdx.x * MT;
    int b = t0 / SEQ;
    float s2 = d_scal[b * 6 + 3], bc2 = d_scal[b * 6 + 4], g2 = d_scal[b * 6 + 5];
    float alpha = 1.f + s2;

#pragma unroll
    for (int rep = 0; rep < MT / 8; rep++) {
        int r = wp * (MT / 8) + rep;
        float4 v = ((const float4*)(d_x2 + (size_t)(t0 + r) * DIM))[lane];
        float s = v.x + v.y + v.z + v.w;
        float sq = v.x * v.x + v.y * v.y + v.z * v.z + v.w * v.w;
        s = warp_sum(s); sq = warp_sum(sq);
        float m = s * (1.f / 128.f);
        float var = sq * (1.f / 128.f) - m * m;
        float r1 = rsqrtf(var + 1e-6f);
        float4 o;
        o.x = alpha * ((v.x - m) * r1) + bc2;
        o.y = alpha * ((v.y - m) * r1) + bc2;
        o.z = alpha * ((v.z - m) * r1) + bc2;
        o.w = alpha * ((v.w - m) * r1) + bc2;
        ((float4*)(A_s + r * 128))[lane] = o;
    }
    __syncthreads();

    int ty = tid / 16, tx = tid % 16, r0 = ty * 4, c0 = tx * 8;
    float accO[4][8];
#pragma unroll
    for (int i = 0; i < 4; i++)
#pragma unroll
        for (int j = 0; j < 8; j++) accO[i][j] = 0.f;

    for (int chunk = 0; chunk < 4; chunk++) {
        // stage W1[:, chunk*128 : chunk*128+128]
        {
            const float4* g4 = (const float4*)w1;
            float4* s4 = (float4*)W_s;
            for (int i = tid; i < 128 * 32; i += 256) {
                int k = i >> 5, nc = i & 31;
                s4[k * 32 + nc] = g4[k * 128 + chunk * 32 + nc];
            }
        }
        __syncthreads();
        float acc[4][8];
#pragma unroll
        for (int i = 0; i < 4; i++)
#pragma unroll
            for (int j = 0; j < 8; j++) acc[i][j] = 0.f;
        gemm_tile(A_s, W_s, acc, r0, c0);
#pragma unroll
        for (int i = 0; i < 4; i++) {
#pragma unroll
            for (int j = 0; j < 8; j++) {
                float hpre = acc[i][j] + b1p[chunk * 128 + c0 + j];
                float t = 0.7978845608028654f * (hpre + 0.044715f * hpre * hpre * hpre);
                G_s[(r0 + i) * 128 + c0 + j] = 0.5f * hpre * (1.f + tanhf(t));
            }
        }
        __syncthreads();
        load_w(W_s, w2 + (size_t)chunk * 128 * 128, tid);
        __syncthreads();
        gemm_tile(G_s, W_s, accO, r0, c0);
        __syncthreads();
    }

#pragma unroll
    for (int i = 0; i < 4; i++) {
        int row = r0 + i;
#pragma unroll
        for (int j = 0; j < 8; j++) {
            int col = c0 + j;
            size_t gi = (size_t)(t0 + row) * DIM + col;
            float m = accO[i][j] + b2p[col];
            out[gi] = d_x2[gi] + g2 * m;
        }
    }
}

// ---------------- host ----------------
extern "C" void kernel_launch(void* const* d_in, const int* in_sizes, int n_in,
                              void* d_out, int out_size) {
    const float* x        = (const float*)d_in[0];
    const float* c        = (const float*)d_in[1];
    const float* cln1_sw  = (const float*)d_in[2];
    const float* cln1_sb  = (const float*)d_in[3];
    const float* cln1_bw  = (const float*)d_in[4];
    const float* cln1_bb  = (const float*)d_in[5];
    const float* gate1_w  = (const float*)d_in[6];
    const float* gate1_b  = (const float*)d_in[7];
    const float* rnn_in_w = (const float*)d_in[8];
    const float* rnn_in_b = (const float*)d_in[9];
    const float* pos_emb  = (const float*)d_in[10];
    const float* rnn_wi   = (const float*)d_in[11];
    const float* rnn_bi   = (const float*)d_in[12];
    const float* rnn_wr   = (const float*)d_in[13];
    const float* rnn_br   = (const float*)d_in[14];
    const float* rnn_a    = (const float*)d_in[15];
    const float* rnn_out_w= (const float*)d_in[16];
    const float* rnn_out_b= (const float*)d_in[17];
    const float* cln2_sw  = (const float*)d_in[18];
    const float* cln2_sb  = (const float*)d_in[19];
    const float* cln2_bw  = (const float*)d_in[20];
    const float* cln2_bb  = (const float*)d_in[21];
    const float* gate2_w  = (const float*)d_in[22];
    const float* gate2_b  = (const float*)d_in[23];
    const float* mlp_w1   = (const float*)d_in[24];
    const float* mlp_b1   = (const float*)d_in[25];
    const float* mlp_w2   = (const float*)d_in[26];
    const float* mlp_b2   = (const float*)d_in[27];
    float* out = (float*)d_out;

    size_t smem_k1 = (size_t)(2 * MT * 128 + 128 * 128) * 4;  // 128 KB
    size_t smem_k5 = (size_t)(MT * 128 + 128 * 128) * 4;      // 96 KB
    size_t smem_k6 = (size_t)(2 * MT * 128 + 128 * 128) * 4;  // 128 KB
    cudaFuncSetAttribute(k1, cudaFuncAttributeMaxDynamicSharedMemorySize, (int)smem_k1);
    cudaFuncSetAttribute(k5, cudaFuncAttributeMaxDynamicSharedMemorySize, (int)smem_k5);
    cudaFuncSetAttribute(k6, cudaFuncAttributeMaxDynamicSharedMemorySize, (int)smem_k6);

    k0<<<1, 256>>>(c,
                   cln1_sw, cln1_sb, cln1_bw, cln1_bb, gate1_w, gate1_b,
                   cln2_sw, cln2_sb, cln2_bw, cln2_bb, gate2_w, gate2_b,
                   rnn_a);
    k1<<<NTOK / MT, 256, smem_k1>>>(x, rnn_in_w, rnn_in_b, pos_emb,
                                    rnn_wi, rnn_bi, rnn_wr, rnn_br);
    k2<<<BSZ * NCH, 128>>>();
    k3<<<BSZ, 128>>>();
    k4<<<BSZ * NCH, 128>>>();
    k5<<<NTOK / MT, 256, smem_k5>>>(x, rnn_out_w, rnn_out_b);
    k6<<<NTOK / MT, 256, smem_k6>>>(mlp_w1, mlp_b1, mlp_w2, mlp_b2, out);
}

// round 4
// speedup vs baseline: 1.1064x; 1.1064x over previous
#include <cuda_runtime.h>

#define BSZ 8
#define SEQ 8192
#define DIM 128
#define NTOK (BSZ*SEQ)
#define MT 64
#define CHUNK 64
#define NCH (SEQ/CHUNK)   // 128

typedef unsigned long long u64;

// ---------------- scratch (static device allocations only) ----------------
__device__ float d_at[NTOK*DIM];
__device__ float d_bt[NTOK*DIM];
__device__ float d_x2[NTOK*DIM];
__device__ float d_cAf[BSZ*NCH*DIM], d_cHf[BSZ*NCH*DIM], d_cHb[BSZ*NCH*DIM];
__device__ float d_inf[BSZ*NCH*DIM], d_inb[BSZ*NCH*DIM];
__device__ float d_scal[BSZ*6];   // per batch: s1,b1,g1,s2,b2,g2
__device__ float d_loga[DIM];

// ---------------- helpers ----------------
__device__ __forceinline__ float warp_sum(float v) {
#pragma unroll
    for (int o = 16; o; o >>= 1) v += __shfl_xor_sync(0xffffffffu, v, o);
    return v;
}
__device__ __forceinline__ float sigm(float v) { return 1.f / (1.f + expf(-v)); }

__device__ __forceinline__ u64 pack2(float a) {
    u64 r;
    asm("mov.b64 %0, {%1, %1};" : "=l"(r) : "r"(__float_as_uint(a)));
    return r;
}
__device__ __forceinline__ float2 unpack2(u64 v) {
    unsigned lo, hi;
    asm("mov.b64 {%0, %1}, %2;" : "=r"(lo), "=r"(hi) : "l"(v));
    return make_float2(__uint_as_float(lo), __uint_as_float(hi));
}
__device__ __forceinline__ void fma2(u64& d, u64 a, u64 b) {
    asm("fma.rn.f32x2 %0, %1, %2, %0;" : "+l"(d) : "l"(a), "l"(b));
}

// load a 128x128 fp32 weight block (row-major, contiguous) into smem
__device__ __forceinline__ void load_w(float* W_s, const float* __restrict__ g, int tid) {
    const float4* g4 = (const float4*)g;
    float4* s4 = (float4*)W_s;
#pragma unroll 4
    for (int i = tid; i < 128 * 32; i += 256) s4[i] = g4[i];
}

// C(64x128) += A(64x128) * W(128x128), packed f32x2. Thread: 4 rows x 8 cols (4 pairs).
__device__ __forceinline__ void gemm_tile2(const float* __restrict__ A_s,
                                           const float* __restrict__ W_s,
                                           u64 acc[4][4], int r0, int c0) {
#pragma unroll 4
    for (int k = 0; k < 128; k++) {
        u64 bv[4];
#pragma unroll
        for (int j = 0; j < 4; j++) bv[j] = *(const u64*)(W_s + k * 128 + c0 + 2 * j);
        u64 av[4];
#pragma unroll
        for (int i = 0; i < 4; i++) av[i] = pack2(A_s[(r0 + i) * 128 + k]);
#pragma unroll
        for (int i = 0; i < 4; i++)
#pragma unroll
            for (int j = 0; j < 4; j++) fma2(acc[i][j], av[i], bv[j]);
    }
}

// ---------------- K0: per-batch conditioning scalars + log(a) ----------------
__global__ void k0(const float* __restrict__ c,
                   const float* w0, const float* b0, const float* w1, const float* b1,
                   const float* w2, const float* b2, const float* w3, const float* b3,
                   const float* w4, const float* b4, const float* w5, const float* b5,
                   const float* __restrict__ rnn_a) {
    const float* ws[6] = {w0, w1, w2, w3, w4, w5};
    const float* bs[6] = {b0, b1, b2, b3, b4, b5};
    int tid = threadIdx.x, lane = tid & 31, wp = tid >> 5;
    for (int idx = wp; idx < 48; idx += 8) {
        int b = idx / 6, j = idx % 6;
        float s = 0.f;
        for (int k = lane; k < 128; k += 32) s += c[b * 128 + k] * ws[j][k];
        s = warp_sum(s);
        if (lane == 0) d_scal[b * 6 + j] = s + bs[j][0];
    }
    if (tid < 128) d_loga[tid] = logf(rnn_a[tid]);
}

// ---------------- K1: LN -> cond -> LN -> u -> gates -> at/bt ----------------
__global__ __launch_bounds__(256) void k1(const float* __restrict__ x,
                                          const float* __restrict__ win, const float* __restrict__ bin,
                                          const float* __restrict__ pos,
                                          const float* __restrict__ wi, const float* __restrict__ bi,
                                          const float* __restrict__ wr, const float* __restrict__ br) {
    extern __shared__ float sm[];
    float* A_s = sm;                  // 64x128  (lnh)
    float* U_s = sm + MT * 128;       // 64x128  (u)
    float* W_s = sm + 2 * MT * 128;   // 128x128
    int tid = threadIdx.x, lane = tid & 31, wp = tid >> 5;
    int t0 = blockIdx.x * MT;
    int b = t0 / SEQ, l0 = t0 % SEQ;
    float s1 = d_scal[b * 6 + 0];
    float alpha = 1.f + s1;
    // bc1 shifts h uniformly; second LN removes the shift (mean(lnx)=0 exactly)

#pragma unroll
    for (int rep = 0; rep < MT / 8; rep++) {
        int r = wp * (MT / 8) + rep;
        float4 v = ((const float4*)(x + (size_t)(t0 + r) * DIM))[lane];
        float s = v.x + v.y + v.z + v.w;
        float sq = v.x * v.x + v.y * v.y + v.z * v.z + v.w * v.w;
        s = warp_sum(s); sq = warp_sum(sq);
        float m = s * (1.f / 128.f);
        float var = sq * (1.f / 128.f) - m * m;
        float r1 = rsqrtf(var + 1e-6f);
        float varln = var * r1 * r1;                        // var/(var+eps)
        float sc = alpha * rsqrtf(alpha * alpha * varln + 1e-6f) * r1;
        float4 o;
        o.x = (v.x - m) * sc; o.y = (v.y - m) * sc;
        o.z = (v.z - m) * sc; o.w = (v.w - m) * sc;
        ((float4*)(A_s + r * 128))[lane] = o;
    }
    __syncthreads();
    load_w(W_s, win, tid);
    __syncthreads();

    int ty = tid / 16, tx = tid % 16, r0 = ty * 4, c0 = tx * 8;
    u64 acc[4][4];
#pragma unroll
    for (int i = 0; i < 4; i++)
#pragma unroll
        for (int j = 0; j < 4; j++) acc[i][j] = 0ull;
    gemm_tile2(A_s, W_s, acc, r0, c0);

    // u = acc + bias + pos_emb
#pragma unroll
    for (int i = 0; i < 4; i++) {
        int row = r0 + i, l = l0 + row;
#pragma unroll
        for (int j = 0; j < 4; j++) {
            float2 p = unpack2(acc[i][j]);
            int col = c0 + 2 * j;
            U_s[row * 128 + col]     = p.x + bin[col]     + pos[(size_t)l * DIM + col];
            U_s[row * 128 + col + 1] = p.y + bin[col + 1] + pos[(size_t)l * DIM + col + 1];
        }
    }
    __syncthreads();
    load_w(W_s, wi, tid);
    __syncthreads();

    u64 acc2[4][4];
#pragma unroll
    for (int i = 0; i < 4; i++)
#pragma unroll
        for (int j = 0; j < 4; j++) acc2[i][j] = 0ull;
    gemm_tile2(U_s, W_s, acc2, r0, c0);
    float giv[4][8];
#pragma unroll
    for (int i = 0; i < 4; i++)
#pragma unroll
        for (int j = 0; j < 4; j++) {
            float2 p = unpack2(acc2[i][j]);
            giv[i][2 * j]     = sigm(p.x + bi[c0 + 2 * j]);
            giv[i][2 * j + 1] = sigm(p.y + bi[c0 + 2 * j + 1]);
        }
    __syncthreads();
    load_w(W_s, wr, tid);
    __syncthreads();

#pragma unroll
    for (int i = 0; i < 4; i++)
#pragma unroll
        for (int j = 0; j < 4; j++) acc2[i][j] = 0ull;
    gemm_tile2(U_s, W_s, acc2, r0, c0);

    float lga[8];
#pragma unroll
    for (int j = 0; j < 8; j++) lga[j] = d_loga[c0 + j];

#pragma unroll
    for (int i = 0; i < 4; i++) {
        int row = r0 + i;
#pragma unroll
        for (int j = 0; j < 4; j++) {
            float2 p = unpack2(acc2[i][j]);
            int col = c0 + 2 * j;
            float gr0 = sigm(p.x + br[col]);
            float gr1 = sigm(p.y + br[col + 1]);
            float at0 = expf(8.f * gr0 * lga[2 * j]);
            float at1 = expf(8.f * gr1 * lga[2 * j + 1]);
            float u0 = U_s[row * 128 + col];
            float u1 = U_s[row * 128 + col + 1];
            float bt0 = sqrtf(fmaxf(1.f - at0 * at0, 0.f)) * giv[i][2 * j] * u0;
            float bt1 = sqrtf(fmaxf(1.f - at1 * at1, 0.f)) * giv[i][2 * j + 1] * u1;
            size_t gi = (size_t)(t0 + row) * DIM + col;
            d_at[gi] = at0; d_at[gi + 1] = at1;
            d_bt[gi] = bt0; d_bt[gi + 1] = bt1;
        }
    }
}

// ---------------- K2: per-chunk carries (fwd + bwd in ONE streaming pass) ----------------
// fwd carry:  Hf = sum_i b_i * prod_{j>i} a_j  (via Hf = a*Hf + b)
// bwd carry:  Hb = sum_i b_i * prod_{j<i} a_j  (via Hb += b*P; P *= a)
// A (both):   P  = prod a
__global__ __launch_bounds__(128) void k2() {
    int b = blockIdx.x / NCH, ch = blockIdx.x % NCH, h = threadIdx.x;
    size_t base = ((size_t)b * SEQ + (size_t)ch * CHUNK) * DIM + h;
    float P = 1.f, Hf = 0.f, Hb = 0.f;
#pragma unroll 1
    for (int i0 = 0; i0 < CHUNK; i0 += 8) {
        float a[8], bb[8];
#pragma unroll
        for (int i = 0; i < 8; i++) {
            size_t idx = base + (size_t)(i0 + i) * DIM;
            a[i] = d_at[idx]; bb[i] = d_bt[idx];
        }
#pragma unroll
        for (int i = 0; i < 8; i++) {
            Hf = fmaf(a[i], Hf, bb[i]);
            Hb = fmaf(bb[i], P, Hb);
            P *= a[i];
        }
    }
    int ci = (b * NCH + ch) * DIM + h;
    d_cAf[ci] = P; d_cHf[ci] = Hf; d_cHb[ci] = Hb;
}

// ---------------- K3: exclusive scan of carries across chunks (reg-preloaded) ----------------
__global__ __launch_bounds__(128) void k3() {
    int b = blockIdx.x, h = threadIdx.x;
    float p = 0.f;
#pragma unroll 1
    for (int c0 = 0; c0 < NCH; c0 += 16) {
        float A[16], H[16];
#pragma unroll
        for (int i = 0; i < 16; i++) {
            int ci = (b * NCH + c0 + i) * DIM + h;
            A[i] = d_cAf[ci]; H[i] = d_cHf[ci];
        }
#pragma unroll
        for (int i = 0; i < 16; i++) {
            int ci = (b * NCH + c0 + i) * DIM + h;
            d_inf[ci] = p;
            p = fmaf(A[i], p, H[i]);
        }
    }
    p = 0.f;
#pragma unroll 1
    for (int c0 = NCH - 16; c0 >= 0; c0 -= 16) {
        float A[16], H[16];
#pragma unroll
        for (int i = 0; i < 16; i++) {
            int ci = (b * NCH + c0 + i) * DIM + h;
            A[i] = d_cAf[ci]; H[i] = d_cHb[ci];
        }
#pragma unroll
        for (int i = 15; i >= 0; i--) {
            int ci = (b * NCH + c0 + i) * DIM + h;
            d_inb[ci] = p;
            p = fmaf(A[i], p, H[i]);
        }
    }
}

// ---------------- K45: apply scan -> smem tiles -> r = [hf|hb]@Wout + b ; x2 = x + g1*r ----
__global__ __launch_bounds__(256) void k45(const float* __restrict__ x,
                                           const float* __restrict__ wout,
                                           const float* __restrict__ bout) {
    extern __shared__ float sm[];
    float* F_s = sm;                  // 64x128 hf
    float* B_s = sm + MT * 128;       // 64x128 hb
    float* W_s = sm + 2 * MT * 128;   // 128x128
    int tid = threadIdx.x;
    int t0 = blockIdx.x * MT;
    int b = t0 / SEQ;
    int ch = (t0 % SEQ) / CHUNK;      // MT == CHUNK: one chunk per block
    float g1 = d_scal[b * 6 + 2];
    size_t base = (size_t)t0 * DIM;

    if (tid < 128) {
        int h = tid;
        float hf = d_inf[(b * NCH + ch) * DIM + h];
#pragma unroll 1
        for (int i0 = 0; i0 < MT; i0 += 8) {
            float a[8], bb[8];
#pragma unroll
            for (int i = 0; i < 8; i++) {
                size_t idx = base + (size_t)(i0 + i) * DIM + h;
                a[i] = d_at[idx]; bb[i] = d_bt[idx];
            }
#pragma unroll
            for (int i = 0; i < 8; i++) {
                hf = fmaf(a[i], hf, bb[i]);
                F_s[(i0 + i) * 128 + h] = hf;
            }
        }
    } else {
        int h = tid - 128;
        float hb = d_inb[(b * NCH + ch) * DIM + h];
#pragma unroll 1
        for (int i0 = MT - 8; i0 >= 0; i0 -= 8) {
            float a[8], bb[8];
#pragma unroll
            for (int i = 0; i < 8; i++) {
                size_t idx = base + (size_t)(i0 + i) * DIM + h;
                a[i] = d_at[idx]; bb[i] = d_bt[idx];
            }
#pragma unroll
            for (int i = 7; i >= 0; i--) {
                hb = fmaf(a[i], hb, bb[i]);
                B_s[(i0 + i) * 128 + h] = hb;
            }
        }
    }
    __syncthreads();

    int ty = tid / 16, tx = tid % 16, r0 = ty * 4, c0 = tx * 8;
    u64 acc[4][4];
#pragma unroll
    for (int i = 0; i < 4; i++)
#pragma unroll
        for (int j = 0; j < 4; j++) acc[i][j] = 0ull;

    load_w(W_s, wout, tid);
    __syncthreads();
    gemm_tile2(F_s, W_s, acc, r0, c0);
    __syncthreads();
    load_w(W_s, wout + 128 * 128, tid);
    __syncthreads();
    gemm_tile2(B_s, W_s, acc, r0, c0);

#pragma unroll
    for (int i = 0; i < 4; i++) {
        int row = r0 + i;
#pragma unroll
        for (int j = 0; j < 4; j++) {
            float2 p = unpack2(acc[i][j]);
            int col = c0 + 2 * j;
            size_t gi = (size_t)(t0 + row) * DIM + col;
            d_x2[gi]     = x[gi]     + g1 * (p.x + bout[col]);
            d_x2[gi + 1] = x[gi + 1] + g1 * (p.y + bout[col + 1]);
        }
    }
}

// ---------------- K6: LN -> cond -> gelu MLP -> out = x2 + g2*m ----------------
__global__ __launch_bounds__(256) void k6(const float* __restrict__ w1, const float* __restrict__ b1p,
                                          const float* __restrict__ w2, const float* __restrict__ b2p,
                                          float* __restrict__ out) {
    extern __shared__ float sm[];
    float* A_s = sm;                  // 64x128 (h2)
    float* G_s = sm + MT * 128;       // 64x128 (gelu act)
    float* W_s = sm + 2 * MT * 128;   // 128x128
    int tid = threadIdx.x, lane = tid & 31, wp = tid >> 5;
    int t0 = blockIdx.x * MT;
    int b = t0 / SEQ;
    float s2 = d_scal[b * 6 + 3], bc2 = d_scal[b * 6 + 4], g2 = d_scal[b * 6 + 5];
    float alpha = 1.f + s2;

#pragma unroll
    for (int rep = 0; rep < MT / 8; rep++) {
        int r = wp * (MT / 8) + rep;
        float4 v = ((const float4*)(d_x2 + (size_t)(t0 + r) * DIM))[lane];
        float s = v.x + v.y + v.z + v.w;
        float sq = v.x * v.x + v.y * v.y + v.z * v.z + v.w * v.w;
        s = warp_sum(s); sq = warp_sum(sq);
        float m = s * (1.f / 128.f);
        float var = sq * (1.f / 128.f) - m * m;
        float r1 = rsqrtf(var + 1e-6f);
        float4 o;
        o.x = alpha * ((v.x - m) * r1) + bc2;
        o.y = alpha * ((v.y - m) * r1) + bc2;
        o.z = alpha * ((v.z - m) * r1) + bc2;
        o.w = alpha * ((v.w - m) * r1) + bc2;
        ((float4*)(A_s + r * 128))[lane] = o;
    }
    __syncthreads();

    int ty = tid / 16, tx = tid % 16, r0 = ty * 4, c0 = tx * 8;
    u64 accO[4][4];
#pragma unroll
    for (int i = 0; i < 4; i++)
#pragma unroll
        for (int j = 0; j < 4; j++) accO[i][j] = 0ull;

    for (int chunk = 0; chunk < 4; chunk++) {
        // stage W1[:, chunk*128 : chunk*128+128]
        {
            const float4* g4 = (const float4*)w1;
            float4* s4 = (float4*)W_s;
            for (int i = tid; i < 128 * 32; i += 256) {
                int k = i >> 5, nc = i & 31;
                s4[k * 32 + nc] = g4[k * 128 + chunk * 32 + nc];
            }
        }
        __syncthreads();
        u64 acc[4][4];
#pragma unroll
        for (int i = 0; i < 4; i++)
#pragma unroll
            for (int j = 0; j < 4; j++) acc[i][j] = 0ull;
        gemm_tile2(A_s, W_s, acc, r0, c0);
#pragma unroll
        for (int i = 0; i < 4; i++) {
#pragma unroll
            for (int j = 0; j < 4; j++) {
                float2 p = unpack2(acc[i][j]);
#pragma unroll
                for (int q = 0; q < 2; q++) {
                    float hpre = (q ? p.y : p.x) + b1p[chunk * 128 + c0 + 2 * j + q];
                    float t = 0.7978845608028654f * (hpre + 0.044715f * hpre * hpre * hpre);
                    G_s[(r0 + i) * 128 + c0 + 2 * j + q] = 0.5f * hpre * (1.f + tanhf(t));
                }
            }
        }
        __syncthreads();
        load_w(W_s, w2 + (size_t)chunk * 128 * 128, tid);
        __syncthreads();
        gemm_tile2(G_s, W_s, accO, r0, c0);
        __syncthreads();
    }

#pragma unroll
    for (int i = 0; i < 4; i++) {
        int row = r0 + i;
#pragma unroll
        for (int j = 0; j < 4; j++) {
            float2 p = unpack2(accO[i][j]);
            int col = c0 + 2 * j;
            size_t gi = (size_t)(t0 + row) * DIM + col;
            out[gi]     = d_x2[gi]     + g2 * (p.x + b2p[col]);
            out[gi + 1] = d_x2[gi + 1] + g2 * (p.y + b2p[col + 1]);
        }
    }
}

// ---------------- host ----------------
extern "C" void kernel_launch(void* const* d_in, const int* in_sizes, int n_in,
                              void* d_out, int out_size) {
    const float* x        = (const float*)d_in[0];
    const float* c        = (const float*)d_in[1];
    const float* cln1_sw  = (const float*)d_in[2];
    const float* cln1_sb  = (const float*)d_in[3];
    const float* cln1_bw  = (const float*)d_in[4];
    const float* cln1_bb  = (const float*)d_in[5];
    const float* gate1_w  = (const float*)d_in[6];
    const float* gate1_b  = (const float*)d_in[7];
    const float* rnn_in_w = (const float*)d_in[8];
    const float* rnn_in_b = (const float*)d_in[9];
    const float* pos_emb  = (const float*)d_in[10];
    const float* rnn_wi   = (const float*)d_in[11];
    const float* rnn_bi   = (const float*)d_in[12];
    const float* rnn_wr   = (const float*)d_in[13];
    const float* rnn_br   = (const float*)d_in[14];
    const float* rnn_a    = (const float*)d_in[15];
    const float* rnn_out_w= (const float*)d_in[16];
    const float* rnn_out_b= (const float*)d_in[17];
    const float* cln2_sw  = (const float*)d_in[18];
    const float* cln2_sb  = (const float*)d_in[19];
    const float* cln2_bw  = (const float*)d_in[20];
    const float* cln2_bb  = (const float*)d_in[21];
    const float* gate2_w  = (const float*)d_in[22];
    const float* gate2_b  = (const float*)d_in[23];
    const float* mlp_w1   = (const float*)d_in[24];
    const float* mlp_b1   = (const float*)d_in[25];
    const float* mlp_w2   = (const float*)d_in[26];
    const float* mlp_b2   = (const float*)d_in[27];
    float* out = (float*)d_out;

    size_t smem_big = (size_t)(2 * MT * 128 + 128 * 128) * 4;  // 128 KB
    cudaFuncSetAttribute(k1,  cudaFuncAttributeMaxDynamicSharedMemorySize, (int)smem_big);
    cudaFuncSetAttribute(k45, cudaFuncAttributeMaxDynamicSharedMemorySize, (int)smem_big);
    cudaFuncSetAttribute(k6,  cudaFuncAttributeMaxDynamicSharedMemorySize, (int)smem_big);

    k0<<<1, 256>>>(c,
                   cln1_sw, cln1_sb, cln1_bw, cln1_bb, gate1_w, gate1_b,
                   cln2_sw, cln2_sb, cln2_bw, cln2_bb, gate2_w, gate2_b,
                   rnn_a);
    k1<<<NTOK / MT, 256, smem_big>>>(x, rnn_in_w, rnn_in_b, pos_emb,
                                     rnn_wi, rnn_bi, rnn_wr, rnn_br);
    k2<<<BSZ * NCH, 128>>>();
    k3<<<BSZ, 128>>>();
    k45<<<NTOK / MT, 256, smem_big>>>(x, rnn_out_w, rnn_out_b);
    k6<<<NTOK / MT, 256, smem_big>>>(mlp_w1, mlp_b1, mlp_w2, mlp_b2, out);
}

// round 5
// speedup vs baseline: 1.5823x; 1.4301x over previous
#include <cuda_runtime.h>

#define BSZ 8
#define SEQ 8192
#define DIM 128
#define NTOK (BSZ*SEQ)
#define MT 64
#define CHUNK 64
#define NCH (SEQ/CHUNK)   // 128
#define AST 132           // padded smem row stride (floats) for activation tiles

typedef unsigned long long u64;

// ---------------- scratch (static device allocations only) ----------------
__device__ float d_at[NTOK*DIM];
__device__ float d_bt[NTOK*DIM];
__device__ float d_x2[NTOK*DIM];
__device__ float d_cAf[BSZ*NCH*DIM], d_cHf[BSZ*NCH*DIM], d_cHb[BSZ*NCH*DIM];
__device__ float d_inf[BSZ*NCH*DIM], d_inb[BSZ*NCH*DIM];
__device__ float d_scal[BSZ*6];   // per batch: s1,b1,g1,s2,b2,g2
__device__ float d_loga[DIM];

// ---------------- helpers ----------------
__device__ __forceinline__ float warp_sum(float v) {
#pragma unroll
    for (int o = 16; o; o >>= 1) v += __shfl_xor_sync(0xffffffffu, v, o);
    return v;
}
__device__ __forceinline__ float sigm(float v) { return 1.f / (1.f + expf(-v)); }

__device__ __forceinline__ u64 pack2(float a) {
    u64 r;
    asm("mov.b64 %0, {%1, %1};" : "=l"(r) : "r"(__float_as_uint(a)));
    return r;
}
__device__ __forceinline__ float2 unpack2(u64 v) {
    unsigned lo, hi;
    asm("mov.b64 {%0, %1}, %2;" : "=r"(lo), "=r"(hi) : "l"(v));
    return make_float2(__uint_as_float(lo), __uint_as_float(hi));
}
__device__ __forceinline__ void fma2(u64& d, u64 a, u64 b) {
    asm("fma.rn.f32x2 %0, %1, %2, %0;" : "+l"(d) : "l"(a), "l"(b));
}

// load a 128x128 fp32 weight block (row-major, contiguous) into smem
__device__ __forceinline__ void load_w(float* W_s, const float* __restrict__ g, int tid) {
    const float4* g4 = (const float4*)g;
    float4* s4 = (float4*)W_s;
#pragma unroll 4
    for (int i = tid; i < 128 * 32; i += 256) s4[i] = g4[i];
}

// C(64x128) += A(64x128,row stride AST) * W(128x128), packed f32x2.
// Thread (ty,tx): rows r0..r0+3, column pairs {tx+16j}, j=0..3 (cols 2*(tx+16j)+q).
// B loads: 16 tx-lanes * 8B contiguous = 128B/wavefront. A loads: LDS.64 spanning 2 k-steps,
// broadcast over tx, bank-conflict-free via AST padding.
__device__ __forceinline__ void gemm_tile2(const float* __restrict__ A_s,
                                           const float* __restrict__ W_s,
                                           u64 acc[4][4], int r0, int tx) {
#pragma unroll 4
    for (int k = 0; k < 128; k += 2) {
        u64 b0[4], b1[4];
#pragma unroll
        for (int j = 0; j < 4; j++) {
            b0[j] = *(const u64*)(W_s + k * 128 + 2 * (tx + 16 * j));
            b1[j] = *(const u64*)(W_s + (k + 1) * 128 + 2 * (tx + 16 * j));
        }
#pragma unroll
        for (int i = 0; i < 4; i++) {
            u64 a2 = *(const u64*)(A_s + (r0 + i) * AST + k);
            float2 av = unpack2(a2);
            u64 alo = pack2(av.x), ahi = pack2(av.y);
#pragma unroll
            for (int j = 0; j < 4; j++) fma2(acc[i][j], alo, b0[j]);
#pragma unroll
            for (int j = 0; j < 4; j++) fma2(acc[i][j], ahi, b1[j]);
        }
    }
}

// ---------------- K0: per-batch conditioning scalars + log(a) ----------------
__global__ void k0(const float* __restrict__ c,
                   const float* w0, const float* b0, const float* w1, const float* b1,
                   const float* w2, const float* b2, const float* w3, const float* b3,
                   const float* w4, const float* b4, const float* w5, const float* b5,
                   const float* __restrict__ rnn_a) {
    const float* ws[6] = {w0, w1, w2, w3, w4, w5};
    const float* bs[6] = {b0, b1, b2, b3, b4, b5};
    int tid = threadIdx.x, lane = tid & 31, wp = tid >> 5;
    for (int idx = wp; idx < 48; idx += 8) {
        int b = idx / 6, j = idx % 6;
        float s = 0.f;
        for (int k = lane; k < 128; k += 32) s += c[b * 128 + k] * ws[j][k];
        s = warp_sum(s);
        if (lane == 0) d_scal[b * 6 + j] = s + bs[j][0];
    }
    if (tid < 128) d_loga[tid] = logf(rnn_a[tid]);
}

// ---------------- K1: LN -> cond -> LN -> u -> gates -> at/bt ----------------
__global__ __launch_bounds__(256) void k1(const float* __restrict__ x,
                                          const float* __restrict__ win, const float* __restrict__ bin,
                                          const float* __restrict__ pos,
                                          const float* __restrict__ wi, const float* __restrict__ bi,
                                          const float* __restrict__ wr, const float* __restrict__ br) {
    extern __shared__ float sm[];
    float* A_s = sm;                      // 64xAST  (lnh)
    float* U_s = sm + MT * AST;           // 64xAST  (u)
    float* W_s = sm + 2 * MT * AST;       // 128x128
    int tid = threadIdx.x, lane = tid & 31, wp = tid >> 5;
    int t0 = blockIdx.x * MT;
    int b = t0 / SEQ, l0 = t0 % SEQ;
    float s1 = d_scal[b * 6 + 0];
    float alpha = 1.f + s1;
    // bc1 shifts h uniformly; second LN removes the shift (mean(lnx)=0 exactly)

#pragma unroll
    for (int rep = 0; rep < MT / 8; rep++) {
        int r = wp * (MT / 8) + rep;
        float4 v = ((const float4*)(x + (size_t)(t0 + r) * DIM))[lane];
        float s = v.x + v.y + v.z + v.w;
        float sq = v.x * v.x + v.y * v.y + v.z * v.z + v.w * v.w;
        s = warp_sum(s); sq = warp_sum(sq);
        float m = s * (1.f / 128.f);
        float var = sq * (1.f / 128.f) - m * m;
        float r1 = rsqrtf(var + 1e-6f);
        float varln = var * r1 * r1;                        // var/(var+eps)
        float sc = alpha * rsqrtf(alpha * alpha * varln + 1e-6f) * r1;
        float4 o;
        o.x = (v.x - m) * sc; o.y = (v.y - m) * sc;
        o.z = (v.z - m) * sc; o.w = (v.w - m) * sc;
        ((float4*)(A_s + r * AST))[lane] = o;
    }
    __syncthreads();
    load_w(W_s, win, tid);
    __syncthreads();

    int ty = tid / 16, tx = tid % 16, r0 = ty * 4;
    u64 acc[4][4];
#pragma unroll
    for (int i = 0; i < 4; i++)
#pragma unroll
        for (int j = 0; j < 4; j++) acc[i][j] = 0ull;
    gemm_tile2(A_s, W_s, acc, r0, tx);

    // u = acc + bias + pos_emb
#pragma unroll
    for (int i = 0; i < 4; i++) {
        int row = r0 + i, l = l0 + row;
#pragma unroll
        for (int j = 0; j < 4; j++) {
            float2 p = unpack2(acc[i][j]);
            int col = 2 * (tx + 16 * j);
            float2 bn = *(const float2*)(bin + col);
            float2 pe = *(const float2*)(pos + (size_t)l * DIM + col);
            U_s[row * AST + col]     = p.x + bn.x + pe.x;
            U_s[row * AST + col + 1] = p.y + bn.y + pe.y;
        }
    }
    __syncthreads();
    load_w(W_s, wi, tid);
    __syncthreads();

    u64 acc2[4][4];
#pragma unroll
    for (int i = 0; i < 4; i++)
#pragma unroll
        for (int j = 0; j < 4; j++) acc2[i][j] = 0ull;
    gemm_tile2(U_s, W_s, acc2, r0, tx);
    float giv[4][8];
#pragma unroll
    for (int i = 0; i < 4; i++)
#pragma unroll
        for (int j = 0; j < 4; j++) {
            float2 p = unpack2(acc2[i][j]);
            int col = 2 * (tx + 16 * j);
            giv[i][2 * j]     = sigm(p.x + bi[col]);
            giv[i][2 * j + 1] = sigm(p.y + bi[col + 1]);
        }
    __syncthreads();
    load_w(W_s, wr, tid);
    __syncthreads();

#pragma unroll
    for (int i = 0; i < 4; i++)
#pragma unroll
        for (int j = 0; j < 4; j++) acc2[i][j] = 0ull;
    gemm_tile2(U_s, W_s, acc2, r0, tx);

    float lga[4][2];
#pragma unroll
    for (int j = 0; j < 4; j++) {
        int col = 2 * (tx + 16 * j);
        lga[j][0] = d_loga[col]; lga[j][1] = d_loga[col + 1];
    }

#pragma unroll
    for (int i = 0; i < 4; i++) {
        int row = r0 + i;
#pragma unroll
        for (int j = 0; j < 4; j++) {
            float2 p = unpack2(acc2[i][j]);
            int col = 2 * (tx + 16 * j);
            float gr0 = sigm(p.x + br[col]);
            float gr1 = sigm(p.y + br[col + 1]);
            float at0 = expf(8.f * gr0 * lga[j][0]);
            float at1 = expf(8.f * gr1 * lga[j][1]);
            float u0 = U_s[row * AST + col];
            float u1 = U_s[row * AST + col + 1];
            float bt0 = sqrtf(fmaxf(1.f - at0 * at0, 0.f)) * giv[i][2 * j] * u0;
            float bt1 = sqrtf(fmaxf(1.f - at1 * at1, 0.f)) * giv[i][2 * j + 1] * u1;
            size_t gi = (size_t)(t0 + row) * DIM + col;
            *(float2*)(d_at + gi) = make_float2(at0, at1);
            *(float2*)(d_bt + gi) = make_float2(bt0, bt1);
        }
    }
}

// ---------------- K2: per-chunk carries (fwd + bwd in ONE streaming pass) ----------------
__global__ __launch_bounds__(128) void k2() {
    int b = blockIdx.x / NCH, ch = blockIdx.x % NCH, h = threadIdx.x;
    size_t base = ((size_t)b * SEQ + (size_t)ch * CHUNK) * DIM + h;
    float P = 1.f, Hf = 0.f, Hb = 0.f;
#pragma unroll 1
    for (int i0 = 0; i0 < CHUNK; i0 += 8) {
        float a[8], bb[8];
#pragma unroll
        for (int i = 0; i < 8; i++) {
            size_t idx = base + (size_t)(i0 + i) * DIM;
            a[i] = d_at[idx]; bb[i] = d_bt[idx];
        }
#pragma unroll
        for (int i = 0; i < 8; i++) {
            Hf = fmaf(a[i], Hf, bb[i]);
            Hb = fmaf(bb[i], P, Hb);
            P *= a[i];
        }
    }
    int ci = (b * NCH + ch) * DIM + h;
    d_cAf[ci] = P; d_cHf[ci] = Hf; d_cHb[ci] = Hb;
}

// ---------------- K3: exclusive scan of carries across chunks (reg-preloaded) ----------------
__global__ __launch_bounds__(128) void k3() {
    int b = blockIdx.x, h = threadIdx.x;
    float p = 0.f;
#pragma unroll 1
    for (int c0 = 0; c0 < NCH; c0 += 16) {
        float A[16], H[16];
#pragma unroll
        for (int i = 0; i < 16; i++) {
            int ci = (b * NCH + c0 + i) * DIM + h;
            A[i] = d_cAf[ci]; H[i] = d_cHf[ci];
        }
#pragma unroll
        for (int i = 0; i < 16; i++) {
            int ci = (b * NCH + c0 + i) * DIM + h;
            d_inf[ci] = p;
            p = fmaf(A[i], p, H[i]);
        }
    }
    p = 0.f;
#pragma unroll 1
    for (int c0 = NCH - 16; c0 >= 0; c0 -= 16) {
        float A[16], H[16];
#pragma unroll
        for (int i = 0; i < 16; i++) {
            int ci = (b * NCH + c0 + i) * DIM + h;
            A[i] = d_cAf[ci]; H[i] = d_cHb[ci];
        }
#pragma unroll
        for (int i = 15; i >= 0; i--) {
            int ci = (b * NCH + c0 + i) * DIM + h;
            d_inb[ci] = p;
            p = fmaf(A[i], p, H[i]);
        }
    }
}

// ---------------- K45: apply scan -> smem tiles -> r = [hf|hb]@Wout + b ; x2 = x + g1*r ----
__global__ __launch_bounds__(256) void k45(const float* __restrict__ x,
                                           const float* __restrict__ wout,
                                           const float* __restrict__ bout) {
    extern __shared__ float sm[];
    float* F_s = sm;                      // 64xAST hf
    float* B_s = sm + MT * AST;           // 64xAST hb
    float* W_s = sm + 2 * MT * AST;       // 128x128
    int tid = threadIdx.x;
    int t0 = blockIdx.x * MT;
    int b = t0 / SEQ;
    int ch = (t0 % SEQ) / CHUNK;          // MT == CHUNK: one chunk per block
    float g1 = d_scal[b * 6 + 2];
    size_t base = (size_t)t0 * DIM;

    if (tid < 128) {
        int h = tid;
        float hf = d_inf[(b * NCH + ch) * DIM + h];
#pragma unroll 1
        for (int i0 = 0; i0 < MT; i0 += 8) {
            float a[8], bb[8];
#pragma unroll
            for (int i = 0; i < 8; i++) {
                size_t idx = base + (size_t)(i0 + i) * DIM + h;
                a[i] = d_at[idx]; bb[i] = d_bt[idx];
            }
#pragma unroll
            for (int i = 0; i < 8; i++) {
                hf = fmaf(a[i], hf, bb[i]);
                F_s[(i0 + i) * AST + h] = hf;
            }
        }
    } else {
        int h = tid - 128;
        float hb = d_inb[(b * NCH + ch) * DIM + h];
#pragma unroll 1
        for (int i0 = MT - 8; i0 >= 0; i0 -= 8) {
            float a[8], bb[8];
#pragma unroll
            for (int i = 0; i < 8; i++) {
                size_t idx = base + (size_t)(i0 + i) * DIM + h;
                a[i] = d_at[idx]; bb[i] = d_bt[idx];
            }
#pragma unroll
            for (int i = 7; i >= 0; i--) {
                hb = fmaf(a[i], hb, bb[i]);
                B_s[(i0 + i) * AST + h] = hb;
            }
        }
    }
    __syncthreads();

    int ty = tid / 16, tx = tid % 16, r0 = ty * 4;
    u64 acc[4][4];
#pragma unroll
    for (int i = 0; i < 4; i++)
#pragma unroll
        for (int j = 0; j < 4; j++) acc[i][j] = 0ull;

    load_w(W_s, wout, tid);
    __syncthreads();
    gemm_tile2(F_s, W_s, acc, r0, tx);
    __syncthreads();
    load_w(W_s, wout + 128 * 128, tid);
    __syncthreads();
    gemm_tile2(B_s, W_s, acc, r0, tx);

#pragma unroll
    for (int i = 0; i < 4; i++) {
        int row = r0 + i;
#pragma unroll
        for (int j = 0; j < 4; j++) {
            float2 p = unpack2(acc[i][j]);
            int col = 2 * (tx + 16 * j);
            size_t gi = (size_t)(t0 + row) * DIM + col;
            float2 xv = *(const float2*)(x + gi);
            float2 bo = *(const float2*)(bout + col);
            float2 o;
            o.x = xv.x + g1 * (p.x + bo.x);
            o.y = xv.y + g1 * (p.y + bo.y);
            *(float2*)(d_x2 + gi) = o;
        }
    }
}

// ---------------- K6: LN -> cond -> gelu MLP -> out = x2 + g2*m ----------------
__global__ __launch_bounds__(256) void k6(const float* __restrict__ w1, const float* __restrict__ b1p,
                                          const float* __restrict__ w2, const float* __restrict__ b2p,
                                          float* __restrict__ out) {
    extern __shared__ float sm[];
    float* A_s = sm;                      // 64xAST (h2)
    float* G_s = sm + MT * AST;           // 64xAST (gelu act)
    float* W_s = sm + 2 * MT * AST;       // 128x128
    int tid = threadIdx.x, lane = tid & 31, wp = tid >> 5;
    int t0 = blockIdx.x * MT;
    int b = t0 / SEQ;
    float s2 = d_scal[b * 6 + 3], bc2 = d_scal[b * 6 + 4], g2 = d_scal[b * 6 + 5];
    float alpha = 1.f + s2;

#pragma unroll
    for (int rep = 0; rep < MT / 8; rep++) {
        int r = wp * (MT / 8) + rep;
        float4 v = ((const float4*)(d_x2 + (size_t)(t0 + r) * DIM))[lane];
        float s = v.x + v.y + v.z + v.w;
        float sq = v.x * v.x + v.y * v.y + v.z * v.z + v.w * v.w;
        s = warp_sum(s); sq = warp_sum(sq);
        float m = s * (1.f / 128.f);
        float var = sq * (1.f / 128.f) - m * m;
        float r1 = rsqrtf(var + 1e-6f);
        float4 o;
        o.x = alpha * ((v.x - m) * r1) + bc2;
        o.y = alpha * ((v.y - m) * r1) + bc2;
        o.z = alpha * ((v.z - m) * r1) + bc2;
        o.w = alpha * ((v.w - m) * r1) + bc2;
        ((float4*)(A_s + r * AST))[lane] = o;
    }
    __syncthreads();

    int ty = tid / 16, tx = tid % 16, r0 = ty * 4;
    u64 accO[4][4];
#pragma unroll
    for (int i = 0; i < 4; i++)
#pragma unroll
        for (int j = 0; j < 4; j++) accO[i][j] = 0ull;

    for (int chunk = 0; chunk < 4; chunk++) {
        // stage W1[:, chunk*128 : chunk*128+128]
        {
            const float4* g4 = (const float4*)w1;
            float4* s4 = (float4*)W_s;
            for (int i = tid; i < 128 * 32; i += 256) {
                int k = i >> 5, nc = i & 31;
                s4[k * 32 + nc] = g4[k * 128 + chunk * 32 + nc];
            }
        }
        __syncthreads();
        u64 acc[4][4];
#pragma unroll
        for (int i = 0; i < 4; i++)
#pragma unroll
            for (int j = 0; j < 4; j++) acc[i][j] = 0ull;
        gemm_tile2(A_s, W_s, acc, r0, tx);
#pragma unroll
        for (int i = 0; i < 4; i++) {
#pragma unroll
            for (int j = 0; j < 4; j++) {
                float2 p = unpack2(acc[i][j]);
                int col = 2 * (tx + 16 * j);
                float2 g;
#pragma unroll
                for (int q = 0; q < 2; q++) {
                    float hpre = (q ? p.y : p.x) + b1p[chunk * 128 + col + q];
                    float t = 0.7978845608028654f * (hpre + 0.044715f * hpre * hpre * hpre);
                    float gv = 0.5f * hpre * (1.f + tanhf(t));
                    if (q) g.y = gv; else g.x = gv;
                }
                *(float2*)(G_s + (r0 + i) * AST + col) = g;
            }
        }
        __syncthreads();
        load_w(W_s, w2 + (size_t)chunk * 128 * 128, tid);
        __syncthreads();
        gemm_tile2(G_s, W_s, accO, r0, tx);
        __syncthreads();
    }

#pragma unroll
    for (int i = 0; i < 4; i++) {
        int row = r0 + i;
#pragma unroll
        for (int j = 0; j < 4; j++) {
            float2 p = unpack2(accO[i][j]);
            int col = 2 * (tx + 16 * j);
            size_t gi = (size_t)(t0 + row) * DIM + col;
            float2 xv = *(const float2*)(d_x2 + gi);
            float2 bo = *(const float2*)(b2p + col);
            float2 o;
            o.x = xv.x + g2 * (p.x + bo.x);
            o.y = xv.y + g2 * (p.y + bo.y);
            *(float2*)(out + gi) = o;
        }
    }
}

// ---------------- host ----------------
extern "C" void kernel_launch(void* const* d_in, const int* in_sizes, int n_in,
                              void* d_out, int out_size) {
    const float* x        = (const float*)d_in[0];
    const float* c        = (const float*)d_in[1];
    const float* cln1_sw  = (const float*)d_in[2];
    const float* cln1_sb  = (const float*)d_in[3];
    const float* cln1_bw  = (const float*)d_in[4];
    const float* cln1_bb  = (const float*)d_in[5];
    const float* gate1_w  = (const float*)d_in[6];
    const float* gate1_b  = (const float*)d_in[7];
    const float* rnn_in_w = (const float*)d_in[8];
    const float* rnn_in_b = (const float*)d_in[9];
    const float* pos_emb  = (const float*)d_in[10];
    const float* rnn_wi   = (const float*)d_in[11];
    const float* rnn_bi   = (const float*)d_in[12];
    const float* rnn_wr   = (const float*)d_in[13];
    const float* rnn_br   = (const float*)d_in[14];
    const float* rnn_a    = (const float*)d_in[15];
    const float* rnn_out_w= (const float*)d_in[16];
    const float* rnn_out_b= (const float*)d_in[17];
    const float* cln2_sw  = (const float*)d_in[18];
    const float* cln2_sb  = (const float*)d_in[19];
    const float* cln2_bw  = (const float*)d_in[20];
    const float* cln2_bb  = (const float*)d_in[21];
    const float* gate2_w  = (const float*)d_in[22];
    const float* gate2_b  = (const float*)d_in[23];
    const float* mlp_w1   = (const float*)d_in[24];
    const float* mlp_b1   = (const float*)d_in[25];
    const float* mlp_w2   = (const float*)d_in[26];
    const float* mlp_b2   = (const float*)d_in[27];
    float* out = (float*)d_out;

    size_t smem_big = (size_t)(2 * MT * AST + 128 * 128) * 4;  // ~130 KB
    cudaFuncSetAttribute(k1,  cudaFuncAttributeMaxDynamicSharedMemorySize, (int)smem_big);
    cudaFuncSetAttribute(k45, cudaFuncAttributeMaxDynamicSharedMemorySize, (int)smem_big);
    cudaFuncSetAttribute(k6,  cudaFuncAttributeMaxDynamicSharedMemorySize, (int)smem_big);

    k0<<<1, 256>>>(c,
                   cln1_sw, cln1_sb, cln1_bw, cln1_bb, gate1_w, gate1_b,
                   cln2_sw, cln2_sb, cln2_bw, cln2_bb, gate2_w, gate2_b,
                   rnn_a);
    k1<<<NTOK / MT, 256, smem_big>>>(x, rnn_in_w, rnn_in_b, pos_emb,
                                     rnn_wi, rnn_bi, rnn_wr, rnn_br);
    k2<<<BSZ * NCH, 128>>>();
    k3<<<BSZ, 128>>>();
    k45<<<NTOK / MT, 256, smem_big>>>(x, rnn_out_w, rnn_out_b);
    k6<<<NTOK / MT, 256, smem_big>>>(mlp_w1, mlp_b1, mlp_w2, mlp_b2, out);
}

// round 7
// speedup vs baseline: 2.3209x; 1.4667x over previous
#include <cuda_runtime.h>
#include <cstdint>

#define BSZ 8
#define SEQ 8192
#define DIM 128
#define NTOK (BSZ*SEQ)
#define MTILE 128
#define NBLK (NTOK/MTILE)   // 512
#define CHUNK 128
#define NCH (SEQ/CHUNK)     // 64
#define WST 132             // padded row stride (floats)
#define TILE_F (128*WST)    // 16896 floats per tile image
#define SMEM_BYTES (3*TILE_F*4)

typedef unsigned int u32;

// ---------------- scratch ----------------
__device__ float d_at[(size_t)DIM*NTOK];   // [h][token] transposed
__device__ float d_bt[(size_t)DIM*NTOK];
__device__ float d_x2[(size_t)NTOK*DIM];
__device__ float d_cAf[BSZ*NCH*DIM], d_cHf[BSZ*NCH*DIM], d_cHb[BSZ*NCH*DIM];
__device__ float d_inf[BSZ*NCH*DIM], d_inb[BSZ*NCH*DIM];
__device__ float d_scal[BSZ*6];
__device__ float d_loga[DIM];
__device__ float d_wimg[13*TILE_F];   // transposed [n][k], tf32-rounded, padded weight images

// ---------------- helpers ----------------
__device__ __forceinline__ u32 smem_u32(const void* p) {
    u32 a; asm("{ .reg .u64 t; cvta.to.shared.u64 t, %1; cvt.u32.u64 %0, t; }" : "=r"(a) : "l"(p));
    return a;
}
__device__ __forceinline__ float warp_sum(float v) {
#pragma unroll
    for (int o = 16; o; o >>= 1) v += __shfl_xor_sync(0xffffffffu, v, o);
    return v;
}
__device__ __forceinline__ float sigm(float v) { return 1.f / (1.f + expf(-v)); }
__device__ __forceinline__ float tf32r(float x) {
    u32 t; asm("cvt.rna.tf32.f32 %0, %1;" : "=r"(t) : "f"(x)); return __uint_as_float(t);
}
__device__ __forceinline__ void ldsm4(u32 addr, u32 r[4]) {
    asm volatile("ldmatrix.sync.aligned.m8n8.x4.shared.b16 {%0,%1,%2,%3}, [%4];"
                 : "=r"(r[0]), "=r"(r[1]), "=r"(r[2]), "=r"(r[3]) : "r"(addr));
}
// A-fragment addr: m16k8 tile at rows rb.., k cols k0.. ; matrices: {r0-7,k0-3},{r8-15,k0-3},{r0-7,k4-7},{r8-15,k4-7}
__device__ __forceinline__ u32 aAddr(u32 base, int lane, int rb, int k0) {
    int row = rb + ((lane >> 3) & 1) * 8 + (lane & 7);
    return base + (u32)(row * (WST * 4) + k0 * 4 + ((lane >> 4) << 4));
}
// B-fragment addr: two n8k8 tiles (n0..n0+15) from Wt[n][k]; matrices: {n0-7,k0-3},{n0-7,k4-7},{n8-15,k0-3},{n8-15,k4-7}
__device__ __forceinline__ u32 bAddr(u32 base, int lane, int n0, int k0) {
    int row = n0 + ((lane >> 4) & 1) * 8 + (lane & 7);
    return base + (u32)(row * (WST * 4) + k0 * 4 + (((lane >> 3) & 1) << 4));
}
__device__ __forceinline__ void mma8(float d[4], const u32 a[4], u32 b0, u32 b1) {
    asm volatile("mma.sync.aligned.m16n8k8.row.col.f32.tf32.tf32.f32 "
                 "{%0,%1,%2,%3}, {%4,%5,%6,%7}, {%8,%9}, {%0,%1,%2,%3};"
                 : "+f"(d[0]), "+f"(d[1]), "+f"(d[2]), "+f"(d[3])
                 : "r"(a[0]), "r"(a[1]), "r"(a[2]), "r"(a[3]), "r"(b0), "r"(b1));
}
// warp GEMM: C(32x64 at rb,cb) += A(128xK128 smem, WST rows) * Wt(n rows, k cols)
__device__ __forceinline__ void wgemm(u32 aBase, u32 wBase, float acc[16][4], int rb, int cb, int lane) {
#pragma unroll 4
    for (int k0 = 0; k0 < 128; k0 += 8) {
        u32 af[2][4], bf[4][4];
        ldsm4(aAddr(aBase, lane, rb, k0), af[0]);
        ldsm4(aAddr(aBase, lane, rb + 16, k0), af[1]);
#pragma unroll
        for (int j = 0; j < 4; j++) ldsm4(bAddr(wBase, lane, cb + 16 * j, k0), bf[j]);
#pragma unroll
        for (int m = 0; m < 2; m++)
#pragma unroll
            for (int nt = 0; nt < 8; nt++)
                mma8(acc[m * 8 + nt], af[m], bf[nt >> 1][(nt & 1) * 2], bf[nt >> 1][(nt & 1) * 2 + 1]);
    }
}
__device__ __forceinline__ void zero_acc(float acc[16][4]) {
#pragma unroll
    for (int i = 0; i < 16; i++)
#pragma unroll
        for (int j = 0; j < 4; j++) acc[i][j] = 0.f;
}
__device__ __forceinline__ void copy_tile(float* dst, const float* __restrict__ src, int tid) {
    const float4* g = (const float4*)src;
    float4* d = (float4*)dst;
    for (int i = tid; i < TILE_F / 4; i += 256) d[i] = g[i];
}

// ---------------- K0: per-batch conditioning scalars + log(a) ----------------
__global__ void k0(const float* __restrict__ c,
                   const float* w0, const float* b0, const float* w1, const float* b1,
                   const float* w2, const float* b2, const float* w3, const float* b3,
                   const float* w4, const float* b4, const float* w5, const float* b5,
                   const float* __restrict__ rnn_a) {
    const float* ws[6] = {w0, w1, w2, w3, w4, w5};
    const float* bs[6] = {b0, b1, b2, b3, b4, b5};
    int tid = threadIdx.x, lane = tid & 31, wp = tid >> 5;
    for (int idx = wp; idx < 48; idx += 8) {
        int b = idx / 6, j = idx % 6;
        float s = 0.f;
        for (int k = lane; k < 128; k += 32) s += c[b * 128 + k] * ws[j][k];
        s = warp_sum(s);
        if (lane == 0) d_scal[b * 6 + j] = s + bs[j][0];
    }
    if (tid < 128) d_loga[tid] = logf(rnn_a[tid]);
}

// ---------------- K0W: build transposed tf32 weight images [n][k] padded WST ----------------
__global__ void k0w(const float* __restrict__ win, const float* __restrict__ wi,
                    const float* __restrict__ wr, const float* __restrict__ wout,
                    const float* __restrict__ w1, const float* __restrict__ w2) {
    int t = blockIdx.x;
    for (int idx = threadIdx.x; idx < 128 * 128; idx += blockDim.x) {
        int n = idx & 127, k = idx >> 7;
        float v;
        if (t == 0)      v = win[k * 128 + n];
        else if (t == 1) v = wi[k * 128 + n];
        else if (t == 2) v = wr[k * 128 + n];
        else if (t == 3) v = wout[k * 128 + n];
        else if (t == 4) v = wout[(128 + k) * 128 + n];
        else if (t < 9)  { int cc = t - 5; v = w1[k * 512 + cc * 128 + n]; }
        else             { int cc = t - 9; v = w2[(cc * 128 + k) * 128 + n]; }
        d_wimg[t * TILE_F + n * WST + k] = tf32r(v);
    }
}

// ---------------- K1: LN->LN -> u -> gates -> at/bt (transposed) ----------------
__global__ __launch_bounds__(256) void k1(const float* __restrict__ x,
                                          const float* __restrict__ binp,
                                          const float* __restrict__ pos,
                                          const float* __restrict__ rbi,
                                          const float* __restrict__ rbr) {
    extern __shared__ float sm[];
    float* A_s = sm;
    float* U_s = sm + TILE_F;
    float* W_s = sm + 2 * TILE_F;
    u32 sbA = smem_u32(A_s), sbU = smem_u32(U_s), sbW = smem_u32(W_s);
    int tid = threadIdx.x, lane = tid & 31, wid = tid >> 5;
    int t0 = blockIdx.x * MTILE;
    int bb = t0 / SEQ, l0 = t0 % SEQ;
    float alpha = 1.f + d_scal[bb * 6 + 0];
    int rb = (wid >> 1) * 32, cb = (wid & 1) * 64;

    // LN(x) + analytic second LN -> A_s (tf32)
#pragma unroll 1
    for (int rep = 0; rep < 16; rep++) {
        int r = wid * 16 + rep;
        float4 v = ((const float4*)(x + (size_t)(t0 + r) * DIM))[lane];
        float s = warp_sum(v.x + v.y + v.z + v.w);
        float sq = warp_sum(v.x * v.x + v.y * v.y + v.z * v.z + v.w * v.w);
        float m = s * (1.f / 128.f);
        float var = sq * (1.f / 128.f) - m * m;
        float r1 = rsqrtf(var + 1e-6f);
        float varln = var * r1 * r1;
        float sc = alpha * rsqrtf(alpha * alpha * varln + 1e-6f) * r1;
        float4 o;
        o.x = tf32r((v.x - m) * sc); o.y = tf32r((v.y - m) * sc);
        o.z = tf32r((v.z - m) * sc); o.w = tf32r((v.w - m) * sc);
        *(float4*)(A_s + r * WST + 4 * lane) = o;
    }
    copy_tile(W_s, d_wimg + 0 * TILE_F, tid);
    __syncthreads();

    float acc[16][4];
    zero_acc(acc);
    wgemm(sbA, sbW, acc, rb, cb, lane);
    __syncthreads();

    // epilogue: u = D + bias + pos -> U_s (tf32)
#pragma unroll
    for (int m = 0; m < 2; m++)
#pragma unroll
        for (int nt = 0; nt < 8; nt++) {
            int row = rb + m * 16 + (lane >> 2);
            int col = cb + nt * 8 + (lane & 3) * 2;
            float* d = acc[m * 8 + nt];
            float2 bn = *(const float2*)(binp + col);
            float2 p0 = *(const float2*)(pos + (size_t)(l0 + row) * DIM + col);
            float2 p1 = *(const float2*)(pos + (size_t)(l0 + row + 8) * DIM + col);
            U_s[row * WST + col]           = tf32r(d[0] + bn.x + p0.x);
            U_s[row * WST + col + 1]       = tf32r(d[1] + bn.y + p0.y);
            U_s[(row + 8) * WST + col]     = tf32r(d[2] + bn.x + p1.x);
            U_s[(row + 8) * WST + col + 1] = tf32r(d[3] + bn.y + p1.y);
        }
    copy_tile(W_s, d_wimg + 1 * TILE_F, tid);
    __syncthreads();

    zero_acc(acc);
    wgemm(sbU, sbW, acc, rb, cb, lane);
    float giv[16][4];
#pragma unroll
    for (int m = 0; m < 2; m++)
#pragma unroll
        for (int nt = 0; nt < 8; nt++) {
            int col = cb + nt * 8 + (lane & 3) * 2;
            float2 bi2 = *(const float2*)(rbi + col);
            float* d = acc[m * 8 + nt];
            giv[m * 8 + nt][0] = sigm(d[0] + bi2.x);
            giv[m * 8 + nt][1] = sigm(d[1] + bi2.y);
            giv[m * 8 + nt][2] = sigm(d[2] + bi2.x);
            giv[m * 8 + nt][3] = sigm(d[3] + bi2.y);
        }
    __syncthreads();
    copy_tile(W_s, d_wimg + 2 * TILE_F, tid);
    __syncthreads();

    zero_acc(acc);
    wgemm(sbU, sbW, acc, rb, cb, lane);

    // gates epilogue -> at/bt in [h][token] layout
#pragma unroll
    for (int m = 0; m < 2; m++)
#pragma unroll
        for (int nt = 0; nt < 8; nt++) {
            int row = rb + m * 16 + (lane >> 2);
            int col = cb + nt * 8 + (lane & 3) * 2;
            float2 br2 = *(const float2*)(rbr + col);
            float la0 = d_loga[col], la1 = d_loga[col + 1];
            float* d = acc[m * 8 + nt];
            float* g = giv[m * 8 + nt];
#pragma unroll
            for (int i = 0; i < 4; i++) {
                int q = i & 1;
                int r2 = row + (i >> 1) * 8;
                float gr = sigm(d[i] + (q ? br2.y : br2.x));
                float at = expf(8.f * gr * (q ? la1 : la0));
                float u = U_s[r2 * WST + col + q];
                float bt = sqrtf(fmaxf(1.f - at * at, 0.f)) * g[i] * u;
                size_t gi = (size_t)(col + q) * NTOK + (t0 + r2);
                d_at[gi] = at;
                d_bt[gi] = bt;
            }
        }
}

// ---------------- K2: per-chunk carries (fwd + bwd, one pass) ----------------
__global__ __launch_bounds__(128) void k2() {
    int b = blockIdx.x / NCH, ch = blockIdx.x % NCH, h = threadIdx.x;
    size_t base = (size_t)h * NTOK + (size_t)b * SEQ + (size_t)ch * CHUNK;
    float P = 1.f, Hf = 0.f, Hb = 0.f;
#pragma unroll 1
    for (int i0 = 0; i0 < CHUNK; i0 += 8) {
        float4 a0 = *(const float4*)(d_at + base + i0);
        float4 a1 = *(const float4*)(d_at + base + i0 + 4);
        float4 b0 = *(const float4*)(d_bt + base + i0);
        float4 b1 = *(const float4*)(d_bt + base + i0 + 4);
        float a[8] = {a0.x, a0.y, a0.z, a0.w, a1.x, a1.y, a1.z, a1.w};
        float bbv[8] = {b0.x, b0.y, b0.z, b0.w, b1.x, b1.y, b1.z, b1.w};
#pragma unroll
        for (int i = 0; i < 8; i++) {
            Hf = fmaf(a[i], Hf, bbv[i]);
            Hb = fmaf(bbv[i], P, Hb);
            P *= a[i];
        }
    }
    int ci = (b * NCH + ch) * DIM + h;
    d_cAf[ci] = P; d_cHf[ci] = Hf; d_cHb[ci] = Hb;
}

// ---------------- K3: exclusive cross-chunk scans ----------------
__global__ __launch_bounds__(128) void k3() {
    int b = blockIdx.x, h = threadIdx.x;
    float p = 0.f;
#pragma unroll 1
    for (int c0 = 0; c0 < NCH; c0 += 16) {
        float A[16], H[16];
#pragma unroll
        for (int i = 0; i < 16; i++) {
            int ci = (b * NCH + c0 + i) * DIM + h;
            A[i] = d_cAf[ci]; H[i] = d_cHf[ci];
        }
#pragma unroll
        for (int i = 0; i < 16; i++) {
            d_inf[(b * NCH + c0 + i) * DIM + h] = p;
            p = fmaf(A[i], p, H[i]);
        }
    }
    p = 0.f;
#pragma unroll 1
    for (int c0 = NCH - 16; c0 >= 0; c0 -= 16) {
        float A[16], H[16];
#pragma unroll
        for (int i = 0; i < 16; i++) {
            int ci = (b * NCH + c0 + i) * DIM + h;
            A[i] = d_cAf[ci]; H[i] = d_cHb[ci];
        }
#pragma unroll
        for (int i = 15; i >= 0; i--) {
            d_inb[(b * NCH + c0 + i) * DIM + h] = p;
            p = fmaf(A[i], p, H[i]);
        }
    }
}

// ---------------- K45: apply scans -> r GEMM -> x2 ----------------
__global__ __launch_bounds__(256) void k45(const float* __restrict__ x,
                                           const float* __restrict__ bout) {
    extern __shared__ float sm[];
    float* F_s = sm;
    float* B_s = sm + TILE_F;
    float* W_s = sm + 2 * TILE_F;
    u32 sbF = smem_u32(F_s), sbB = smem_u32(B_s), sbW = smem_u32(W_s);
    int tid = threadIdx.x, lane = tid & 31, wid = tid >> 5;
    int t0 = blockIdx.x * MTILE;
    int bb = t0 / SEQ, ch = (t0 % SEQ) / CHUNK;
    float g1 = d_scal[bb * 6 + 2];
    int rb = (wid >> 1) * 32, cb = (wid & 1) * 64;

    if (tid < 128) {
        int h = tid;
        size_t base = (size_t)h * NTOK + t0;
        float hf = d_inf[(bb * NCH + ch) * DIM + h];
#pragma unroll 1
        for (int i0 = 0; i0 < MTILE; i0 += 8) {
            float4 a0 = *(const float4*)(d_at + base + i0);
            float4 a1 = *(const float4*)(d_at + base + i0 + 4);
            float4 b0 = *(const float4*)(d_bt + base + i0);
            float4 b1 = *(const float4*)(d_bt + base + i0 + 4);
            float a[8] = {a0.x, a0.y, a0.z, a0.w, a1.x, a1.y, a1.z, a1.w};
            float bv[8] = {b0.x, b0.y, b0.z, b0.w, b1.x, b1.y, b1.z, b1.w};
#pragma unroll
            for (int i = 0; i < 8; i++) {
                hf = fmaf(a[i], hf, bv[i]);
                F_s[(i0 + i) * WST + h] = tf32r(hf);
            }
        }
    } else {
        int h = tid - 128;
        size_t base = (size_t)h * NTOK + t0;
        float hb = d_inb[(bb * NCH + ch) * DIM + h];
#pragma unroll 1
        for (int i0 = MTILE - 8; i0 >= 0; i0 -= 8) {
            float4 a0 = *(const float4*)(d_at + base + i0);
            float4 a1 = *(const float4*)(d_at + base + i0 + 4);
            float4 b0 = *(const float4*)(d_bt + base + i0);
            float4 b1 = *(const float4*)(d_bt + base + i0 + 4);
            float a[8] = {a0.x, a0.y, a0.z, a0.w, a1.x, a1.y, a1.z, a1.w};
            float bv[8] = {b0.x, b0.y, b0.z, b0.w, b1.x, b1.y, b1.z, b1.w};
#pragma unroll
            for (int i = 7; i >= 0; i--) {
                hb = fmaf(a[i], hb, bv[i]);
                B_s[(i0 + i) * WST + h] = tf32r(hb);
            }
        }
    }
    copy_tile(W_s, d_wimg + 3 * TILE_F, tid);
    __syncthreads();

    float acc[16][4];
    zero_acc(acc);
    wgemm(sbF, sbW, acc, rb, cb, lane);
    __syncthreads();
    copy_tile(W_s, d_wimg + 4 * TILE_F, tid);
    __syncthreads();
    wgemm(sbB, sbW, acc, rb, cb, lane);

#pragma unroll
    for (int m = 0; m < 2; m++)
#pragma unroll
        for (int nt = 0; nt < 8; nt++) {
            int row = rb + m * 16 + (lane >> 2);
            int col = cb + nt * 8 + (lane & 3) * 2;
            float* d = acc[m * 8 + nt];
            float2 bo = *(const float2*)(bout + col);
            size_t g0 = (size_t)(t0 + row) * DIM + col;
            size_t g1i = (size_t)(t0 + row + 8) * DIM + col;
            float2 x0 = *(const float2*)(x + g0);
            float2 x1 = *(const float2*)(x + g1i);
            float2 o0, o1;
            o0.x = x0.x + g1 * (d[0] + bo.x);
            o0.y = x0.y + g1 * (d[1] + bo.y);
            o1.x = x1.x + g1 * (d[2] + bo.x);
            o1.y = x1.y + g1 * (d[3] + bo.y);
            *(float2*)(d_x2 + g0) = o0;
            *(float2*)(d_x2 + g1i) = o1;
        }
}

// ---------------- K6: LN -> gelu MLP -> out ----------------
__global__ __launch_bounds__(256) void k6(const float* __restrict__ b1p,
                                          const float* __restrict__ b2p,
                                          float* __restrict__ out) {
    extern __shared__ float sm[];
    float* A_s = sm;
    float* G_s = sm + TILE_F;
    float* W_s = sm + 2 * TILE_F;
    u32 sbA = smem_u32(A_s), sbG = smem_u32(G_s), sbW = smem_u32(W_s);
    int tid = threadIdx.x, lane = tid & 31, wid = tid >> 5;
    int t0 = blockIdx.x * MTILE;
    int bb = t0 / SEQ;
    float alpha = 1.f + d_scal[bb * 6 + 3];
    float bc2 = d_scal[bb * 6 + 4], g2 = d_scal[bb * 6 + 5];
    int rb = (wid >> 1) * 32, cb = (wid & 1) * 64;

#pragma unroll 1
    for (int rep = 0; rep < 16; rep++) {
        int r = wid * 16 + rep;
        float4 v = ((const float4*)(d_x2 + (size_t)(t0 + r) * DIM))[lane];
        float s = warp_sum(v.x + v.y + v.z + v.w);
        float sq = warp_sum(v.x * v.x + v.y * v.y + v.z * v.z + v.w * v.w);
        float m = s * (1.f / 128.f);
        float var = sq * (1.f / 128.f) - m * m;
        float r1 = rsqrtf(var + 1e-6f);
        float4 o;
        o.x = tf32r(alpha * ((v.x - m) * r1) + bc2);
        o.y = tf32r(alpha * ((v.y - m) * r1) + bc2);
        o.z = tf32r(alpha * ((v.z - m) * r1) + bc2);
        o.w = tf32r(alpha * ((v.w - m) * r1) + bc2);
        *(float4*)(A_s + r * WST + 4 * lane) = o;
    }

    float accO[16][4];
    zero_acc(accO);

#pragma unroll 1
    for (int c = 0; c < 4; c++) {
        copy_tile(W_s, d_wimg + (5 + c) * TILE_F, tid);
        __syncthreads();
        float acc[16][4];
        zero_acc(acc);
        wgemm(sbA, sbW, acc, rb, cb, lane);
        __syncthreads();
        // gelu epilogue -> G_s
#pragma unroll
        for (int m = 0; m < 2; m++)
#pragma unroll
            for (int nt = 0; nt < 8; nt++) {
                int row = rb + m * 16 + (lane >> 2);
                int col = cb + nt * 8 + (lane & 3) * 2;
                float2 bn = *(const float2*)(b1p + c * 128 + col);
                float* d = acc[m * 8 + nt];
#pragma unroll
                for (int i = 0; i < 4; i++) {
                    int q = i & 1;
                    int r2 = row + (i >> 1) * 8;
                    float hpre = d[i] + (q ? bn.y : bn.x);
                    float t = 0.7978845608028654f * (hpre + 0.044715f * hpre * hpre * hpre);
                    G_s[r2 * WST + col + q] = tf32r(0.5f * hpre * (1.f + tanhf(t)));
                }
            }
        copy_tile(W_s, d_wimg + (9 + c) * TILE_F, tid);
        __syncthreads();
        wgemm(sbG, sbW, accO, rb, cb, lane);
        __syncthreads();
    }

#pragma unroll
    for (int m = 0; m < 2; m++)
#pragma unroll
        for (int nt = 0; nt < 8; nt++) {
            int row = rb + m * 16 + (lane >> 2);
            int col = cb + nt * 8 + (lane & 3) * 2;
            float* d = accO[m * 8 + nt];
            float2 bo = *(const float2*)(b2p + col);
            size_t g0 = (size_t)(t0 + row) * DIM + col;
            size_t g1i = (size_t)(t0 + row + 8) * DIM + col;
            float2 x0 = *(const float2*)(d_x2 + g0);
            float2 x1 = *(const float2*)(d_x2 + g1i);
            float2 o0, o1;
            o0.x = x0.x + g2 * (d[0] + bo.x);
            o0.y = x0.y + g2 * (d[1] + bo.y);
            o1.x = x1.x + g2 * (d[2] + bo.x);
            o1.y = x1.y + g2 * (d[3] + bo.y);
            *(float2*)(out + g0) = o0;
            *(float2*)(out + g1i) = o1;
        }
}

// ---------------- host ----------------
extern "C" void kernel_launch(void* const* d_in, const int* in_sizes, int n_in,
                              void* d_out, int out_size) {
    const float* x        = (const float*)d_in[0];
    const float* c        = (const float*)d_in[1];
    const float* cln1_sw  = (const float*)d_in[2];
    const float* cln1_sb  = (const float*)d_in[3];
    const float* cln1_bw  = (const float*)d_in[4];
    const float* cln1_bb  = (const float*)d_in[5];
    const float* gate1_w  = (const float*)d_in[6];
    const float* gate1_b  = (const float*)d_in[7];
    const float* rnn_in_w = (const float*)d_in[8];
    const float* rnn_in_b = (const float*)d_in[9];
    const float* pos_emb  = (const float*)d_in[10];
    const float* rnn_wi   = (const float*)d_in[11];
    const float* rnn_bi   = (const float*)d_in[12];
    const float* rnn_wr   = (const float*)d_in[13];
    const float* rnn_br   = (const float*)d_in[14];
    const float* rnn_a    = (const float*)d_in[15];
    const float* rnn_out_w= (const float*)d_in[16];
    const float* rnn_out_b= (const float*)d_in[17];
    const float* cln2_sw  = (const float*)d_in[18];
    const float* cln2_sb  = (const float*)d_in[19];
    const float* cln2_bw  = (const float*)d_in[20];
    const float* cln2_bb  = (const float*)d_in[21];
    const float* gate2_w  = (const float*)d_in[22];
    const float* gate2_b  = (const float*)d_in[23];
    const float* mlp_w1   = (const float*)d_in[24];
    const float* mlp_b1   = (const float*)d_in[25];
    const float* mlp_w2   = (const float*)d_in[26];
    const float* mlp_b2   = (const float*)d_in[27];
    float* out = (float*)d_out;

    cudaFuncSetAttribute(k1,  cudaFuncAttributeMaxDynamicSharedMemorySize, SMEM_BYTES);
    cudaFuncSetAttribute(k45, cudaFuncAttributeMaxDynamicSharedMemorySize, SMEM_BYTES);
    cudaFuncSetAttribute(k6,  cudaFuncAttributeMaxDynamicSharedMemorySize, SMEM_BYTES);

    k0<<<1, 256>>>(c,
                   cln1_sw, cln1_sb, cln1_bw, cln1_bb, gate1_w, gate1_b,
                   cln2_sw, cln2_sb, cln2_bw, cln2_bb, gate2_w, gate2_b,
                   rnn_a);
    k0w<<<13, 256>>>(rnn_in_w, rnn_wi, rnn_wr, rnn_out_w, mlp_w1, mlp_w2);
    k1<<<NBLK, 256, SMEM_BYTES>>>(x, rnn_in_b, pos_emb, rnn_bi, rnn_br);
    k2<<<BSZ * NCH, 128>>>();
    k3<<<BSZ, 128>>>();
    k45<<<NBLK, 256, SMEM_BYTES>>>(x, rnn_out_b);
    k6<<<NBLK, 256, SMEM_BYTES>>>(mlp_b1, mlp_b2, out);
}

// round 8
// speedup vs baseline: 2.5704x; 1.1075x over previous
#include <cuda_runtime.h>
#include <cstdint>

#define BSZ 8
#define SEQ 8192
#define DIM 128
#define NTOK (BSZ*SEQ)
#define MTILE 128
#define NBLK (NTOK/MTILE)   // 512
#define CHUNK 128
#define NCH (SEQ/CHUNK)     // 64
#define WST 132             // padded row stride (floats)
#define TILE_F (128*WST)    // 16896 floats per tile image
#define SMEM_BYTES (3*TILE_F*4)

typedef unsigned int u32;

// ---------------- scratch ----------------
__device__ float d_at[(size_t)DIM*NTOK];   // [h][token] transposed
__device__ float d_bt[(size_t)DIM*NTOK];
__device__ float d_x2[(size_t)NTOK*DIM];
__device__ float d_cAf[BSZ*NCH*DIM], d_cHf[BSZ*NCH*DIM], d_cHb[BSZ*NCH*DIM];
__device__ float d_inf[BSZ*NCH*DIM], d_inb[BSZ*NCH*DIM];
__device__ float d_scal[BSZ*6];
__device__ float d_loga[DIM];
__device__ float d_wimg[13*TILE_F];   // transposed [n][k], tf32-rounded, padded weight images

// ---------------- helpers ----------------
__device__ __forceinline__ u32 smem_u32(const void* p) {
    u32 a; asm("{ .reg .u64 t; cvta.to.shared.u64 t, %1; cvt.u32.u64 %0, t; }" : "=r"(a) : "l"(p));
    return a;
}
__device__ __forceinline__ float warp_sum(float v) {
#pragma unroll
    for (int o = 16; o; o >>= 1) v += __shfl_xor_sync(0xffffffffu, v, o);
    return v;
}
// fast transcendentals (MUFU-based)
__device__ __forceinline__ float sigm(float v) { return __fdividef(1.f, 1.f + __expf(-v)); }
__device__ __forceinline__ float tanh_ap(float x) {
    float r; asm("tanh.approx.f32 %0, %1;" : "=f"(r) : "f"(x)); return r;
}
__device__ __forceinline__ float sqrt_ap(float x) {
    float r; asm("sqrt.approx.f32 %0, %1;" : "=f"(r) : "f"(x)); return r;
}
__device__ __forceinline__ float tf32r(float x) {
    u32 t; asm("cvt.rna.tf32.f32 %0, %1;" : "=r"(t) : "f"(x)); return __uint_as_float(t);
}
__device__ __forceinline__ void ldsm4(u32 addr, u32 r[4]) {
    asm volatile("ldmatrix.sync.aligned.m8n8.x4.shared.b16 {%0,%1,%2,%3}, [%4];"
                 : "=r"(r[0]), "=r"(r[1]), "=r"(r[2]), "=r"(r[3]) : "r"(addr));
}
__device__ __forceinline__ u32 aAddr(u32 base, int lane, int rb, int k0) {
    int row = rb + ((lane >> 3) & 1) * 8 + (lane & 7);
    return base + (u32)(row * (WST * 4) + k0 * 4 + ((lane >> 4) << 4));
}
__device__ __forceinline__ u32 bAddr(u32 base, int lane, int n0, int k0) {
    int row = n0 + ((lane >> 4) & 1) * 8 + (lane & 7);
    return base + (u32)(row * (WST * 4) + k0 * 4 + (((lane >> 3) & 1) << 4));
}
__device__ __forceinline__ void mma8(float d[4], const u32 a[4], u32 b0, u32 b1) {
    asm volatile("mma.sync.aligned.m16n8k8.row.col.f32.tf32.tf32.f32 "
                 "{%0,%1,%2,%3}, {%4,%5,%6,%7}, {%8,%9}, {%0,%1,%2,%3};"
                 : "+f"(d[0]), "+f"(d[1]), "+f"(d[2]), "+f"(d[3])
                 : "r"(a[0]), "r"(a[1]), "r"(a[2]), "r"(a[3]), "r"(b0), "r"(b1));
}
__device__ __forceinline__ void wgemm(u32 aBase, u32 wBase, float acc[16][4], int rb, int cb, int lane) {
#pragma unroll 4
    for (int k0 = 0; k0 < 128; k0 += 8) {
        u32 af[2][4], bf[4][4];
        ldsm4(aAddr(aBase, lane, rb, k0), af[0]);
        ldsm4(aAddr(aBase, lane, rb + 16, k0), af[1]);
#pragma unroll
        for (int j = 0; j < 4; j++) ldsm4(bAddr(wBase, lane, cb + 16 * j, k0), bf[j]);
#pragma unroll
        for (int m = 0; m < 2; m++)
#pragma unroll
            for (int nt = 0; nt < 8; nt++)
                mma8(acc[m * 8 + nt], af[m], bf[nt >> 1][(nt & 1) * 2], bf[nt >> 1][(nt & 1) * 2 + 1]);
    }
}
__device__ __forceinline__ void zero_acc(float acc[16][4]) {
#pragma unroll
    for (int i = 0; i < 16; i++)
#pragma unroll
        for (int j = 0; j < 4; j++) acc[i][j] = 0.f;
}
__device__ __forceinline__ void copy_tile(float* dst, const float* __restrict__ src, int tid) {
    const float4* g = (const float4*)src;
    float4* d = (float4*)dst;
    for (int i = tid; i < TILE_F / 4; i += 256) d[i] = g[i];
}

// ---------------- K0: per-batch conditioning scalars + log(a) ----------------
__global__ void k0(const float* __restrict__ c,
                   const float* w0, const float* b0, const float* w1, const float* b1,
                   const float* w2, const float* b2, const float* w3, const float* b3,
                   const float* w4, const float* b4, const float* w5, const float* b5,
                   const float* __restrict__ rnn_a) {
    const float* ws[6] = {w0, w1, w2, w3, w4, w5};
    const float* bs[6] = {b0, b1, b2, b3, b4, b5};
    int tid = threadIdx.x, lane = tid & 31, wp = tid >> 5;
    for (int idx = wp; idx < 48; idx += 8) {
        int b = idx / 6, j = idx % 6;
        float s = 0.f;
        for (int k = lane; k < 128; k += 32) s += c[b * 128 + k] * ws[j][k];
        s = warp_sum(s);
        if (lane == 0) d_scal[b * 6 + j] = s + bs[j][0];
    }
    if (tid < 128) d_loga[tid] = logf(rnn_a[tid]);
}

// ---------------- K0W: build transposed tf32 weight images [n][k] padded WST ----------------
__global__ void k0w(const float* __restrict__ win, const float* __restrict__ wi,
                    const float* __restrict__ wr, const float* __restrict__ wout,
                    const float* __restrict__ w1, const float* __restrict__ w2) {
    int t = blockIdx.x;
    for (int idx = threadIdx.x; idx < 128 * 128; idx += blockDim.x) {
        int n = idx & 127, k = idx >> 7;
        float v;
        if (t == 0)      v = win[k * 128 + n];
        else if (t == 1) v = wi[k * 128 + n];
        else if (t == 2) v = wr[k * 128 + n];
        else if (t == 3) v = wout[k * 128 + n];
        else if (t == 4) v = wout[(128 + k) * 128 + n];
        else if (t < 9)  { int cc = t - 5; v = w1[k * 512 + cc * 128 + n]; }
        else             { int cc = t - 9; v = w2[(cc * 128 + k) * 128 + n]; }
        d_wimg[t * TILE_F + n * WST + k] = tf32r(v);
    }
}

// ---------------- K1: LN->LN -> u -> gates -> at/bt + fused chunk carries ----------------
__global__ __launch_bounds__(256) void k1(const float* __restrict__ x,
                                          const float* __restrict__ binp,
                                          const float* __restrict__ pos,
                                          const float* __restrict__ rbi,
                                          const float* __restrict__ rbr) {
    extern __shared__ float sm[];
    float* A_s = sm;
    float* U_s = sm + TILE_F;
    float* W_s = sm + 2 * TILE_F;
    u32 sbA = smem_u32(A_s), sbU = smem_u32(U_s), sbW = smem_u32(W_s);
    int tid = threadIdx.x, lane = tid & 31, wid = tid >> 5;
    int t0 = blockIdx.x * MTILE;
    int bb = t0 / SEQ, l0 = t0 % SEQ;
    int ch = l0 / CHUNK;   // MTILE == CHUNK
    float alpha = 1.f + d_scal[bb * 6 + 0];
    int rb = (wid >> 1) * 32, cb = (wid & 1) * 64;

    // LN(x) + analytic second LN -> A_s (tf32)
#pragma unroll 1
    for (int rep = 0; rep < 16; rep++) {
        int r = wid * 16 + rep;
        float4 v = ((const float4*)(x + (size_t)(t0 + r) * DIM))[lane];
        float s = warp_sum(v.x + v.y + v.z + v.w);
        float sq = warp_sum(v.x * v.x + v.y * v.y + v.z * v.z + v.w * v.w);
        float m = s * (1.f / 128.f);
        float var = sq * (1.f / 128.f) - m * m;
        float r1 = rsqrtf(var + 1e-6f);
        float varln = var * r1 * r1;
        float sc = alpha * rsqrtf(alpha * alpha * varln + 1e-6f) * r1;
        float4 o;
        o.x = tf32r((v.x - m) * sc); o.y = tf32r((v.y - m) * sc);
        o.z = tf32r((v.z - m) * sc); o.w = tf32r((v.w - m) * sc);
        *(float4*)(A_s + r * WST + 4 * lane) = o;
    }
    copy_tile(W_s, d_wimg + 0 * TILE_F, tid);
    __syncthreads();

    float acc[16][4];
    zero_acc(acc);
    wgemm(sbA, sbW, acc, rb, cb, lane);
    __syncthreads();

    // epilogue: u = D + bias + pos -> U_s (tf32)
#pragma unroll
    for (int m = 0; m < 2; m++)
#pragma unroll
        for (int nt = 0; nt < 8; nt++) {
            int row = rb + m * 16 + (lane >> 2);
            int col = cb + nt * 8 + (lane & 3) * 2;
            float* d = acc[m * 8 + nt];
            float2 bn = *(const float2*)(binp + col);
            float2 p0 = *(const float2*)(pos + (size_t)(l0 + row) * DIM + col);
            float2 p1 = *(const float2*)(pos + (size_t)(l0 + row + 8) * DIM + col);
            U_s[row * WST + col]           = tf32r(d[0] + bn.x + p0.x);
            U_s[row * WST + col + 1]       = tf32r(d[1] + bn.y + p0.y);
            U_s[(row + 8) * WST + col]     = tf32r(d[2] + bn.x + p1.x);
            U_s[(row + 8) * WST + col + 1] = tf32r(d[3] + bn.y + p1.y);
        }
    copy_tile(W_s, d_wimg + 1 * TILE_F, tid);
    __syncthreads();

    zero_acc(acc);
    wgemm(sbU, sbW, acc, rb, cb, lane);
    float giv[16][4];
#pragma unroll
    for (int m = 0; m < 2; m++)
#pragma unroll
        for (int nt = 0; nt < 8; nt++) {
            int col = cb + nt * 8 + (lane & 3) * 2;
            float2 bi2 = *(const float2*)(rbi + col);
            float* d = acc[m * 8 + nt];
            giv[m * 8 + nt][0] = sigm(d[0] + bi2.x);
            giv[m * 8 + nt][1] = sigm(d[1] + bi2.y);
            giv[m * 8 + nt][2] = sigm(d[2] + bi2.x);
            giv[m * 8 + nt][3] = sigm(d[3] + bi2.y);
        }
    __syncthreads();
    copy_tile(W_s, d_wimg + 2 * TILE_F, tid);
    __syncthreads();

    zero_acc(acc);
    wgemm(sbU, sbW, acc, rb, cb, lane);
    __syncthreads();   // close W_s read hazard before epilogue reuses A_s/W_s as at/bt tiles

    // gates epilogue -> at/bt to global [h][token] AND smem (A_s=at, W_s=bt) for fused carries
#pragma unroll
    for (int m = 0; m < 2; m++)
#pragma unroll
        for (int nt = 0; nt < 8; nt++) {
            int row = rb + m * 16 + (lane >> 2);
            int col = cb + nt * 8 + (lane & 3) * 2;
            float2 br2 = *(const float2*)(rbr + col);
            float la0 = d_loga[col], la1 = d_loga[col + 1];
            float* d = acc[m * 8 + nt];
            float* g = giv[m * 8 + nt];
#pragma unroll
            for (int i = 0; i < 4; i++) {
                int q = i & 1;
                int r2 = row + (i >> 1) * 8;
                float gr = sigm(d[i] + (q ? br2.y : br2.x));
                float at = __expf(8.f * gr * (q ? la1 : la0));
                float u = U_s[r2 * WST + col + q];
                float bt = sqrt_ap(fmaxf(1.f - at * at, 0.f)) * g[i] * u;
                size_t gi = (size_t)(col + q) * NTOK + (t0 + r2);
                d_at[gi] = at;
                d_bt[gi] = bt;
                A_s[r2 * WST + col + q] = at;
                W_s[r2 * WST + col + q] = bt;
            }
        }
    __syncthreads();

    // fused K2: per-chunk carries from smem (threads 0-127, one per h)
    if (tid < 128) {
        int h = tid;
        float P = 1.f, Hf = 0.f, Hb = 0.f;
#pragma unroll 1
        for (int i0 = 0; i0 < CHUNK; i0 += 8) {
            float a[8], bv[8];
#pragma unroll
            for (int i = 0; i < 8; i++) {
                a[i] = A_s[(i0 + i) * WST + h];
                bv[i] = W_s[(i0 + i) * WST + h];
            }
#pragma unroll
            for (int i = 0; i < 8; i++) {
                Hf = fmaf(a[i], Hf, bv[i]);
                Hb = fmaf(bv[i], P, Hb);
                P *= a[i];
            }
        }
        int ci = (bb * NCH + ch) * DIM + h;
        d_cAf[ci] = P; d_cHf[ci] = Hf; d_cHb[ci] = Hb;
    }
}

// ---------------- K3: exclusive cross-chunk scans (fwd/bwd concurrent) ----------------
__global__ __launch_bounds__(256) void k3() {
    int b = blockIdx.x, tid = threadIdx.x;
    int h = tid & 127;
    if (tid < 128) {
        float p = 0.f;
#pragma unroll 1
        for (int c0 = 0; c0 < NCH; c0 += 16) {
            float A[16], H[16];
#pragma unroll
            for (int i = 0; i < 16; i++) {
                int ci = (b * NCH + c0 + i) * DIM + h;
                A[i] = d_cAf[ci]; H[i] = d_cHf[ci];
            }
#pragma unroll
            for (int i = 0; i < 16; i++) {
                d_inf[(b * NCH + c0 + i) * DIM + h] = p;
                p = fmaf(A[i], p, H[i]);
            }
        }
    } else {
        float p = 0.f;
#pragma unroll 1
        for (int c0 = NCH - 16; c0 >= 0; c0 -= 16) {
            float A[16], H[16];
#pragma unroll
            for (int i = 0; i < 16; i++) {
                int ci = (b * NCH + c0 + i) * DIM + h;
                A[i] = d_cAf[ci]; H[i] = d_cHb[ci];
            }
#pragma unroll
            for (int i = 15; i >= 0; i--) {
                d_inb[(b * NCH + c0 + i) * DIM + h] = p;
                p = fmaf(A[i], p, H[i]);
            }
        }
    }
}

// ---------------- K45: apply scans -> r GEMM -> x2 ----------------
__global__ __launch_bounds__(256) void k45(const float* __restrict__ x,
                                           const float* __restrict__ bout) {
    extern __shared__ float sm[];
    float* F_s = sm;
    float* B_s = sm + TILE_F;
    float* W_s = sm + 2 * TILE_F;
    u32 sbF = smem_u32(F_s), sbB = smem_u32(B_s), sbW = smem_u32(W_s);
    int tid = threadIdx.x, lane = tid & 31, wid = tid >> 5;
    int t0 = blockIdx.x * MTILE;
    int bb = t0 / SEQ, ch = (t0 % SEQ) / CHUNK;
    float g1 = d_scal[bb * 6 + 2];
    int rb = (wid >> 1) * 32, cb = (wid & 1) * 64;

    if (tid < 128) {
        int h = tid;
        size_t base = (size_t)h * NTOK + t0;
        float hf = d_inf[(bb * NCH + ch) * DIM + h];
#pragma unroll 1
        for (int i0 = 0; i0 < MTILE; i0 += 8) {
            float4 a0 = *(const float4*)(d_at + base + i0);
            float4 a1 = *(const float4*)(d_at + base + i0 + 4);
            float4 b0 = *(const float4*)(d_bt + base + i0);
            float4 b1 = *(const float4*)(d_bt + base + i0 + 4);
            float a[8] = {a0.x, a0.y, a0.z, a0.w, a1.x, a1.y, a1.z, a1.w};
            float bv[8] = {b0.x, b0.y, b0.z, b0.w, b1.x, b1.y, b1.z, b1.w};
#pragma unroll
            for (int i = 0; i < 8; i++) {
                hf = fmaf(a[i], hf, bv[i]);
                F_s[(i0 + i) * WST + h] = tf32r(hf);
            }
        }
    } else {
        int h = tid - 128;
        size_t base = (size_t)h * NTOK + t0;
        float hb = d_inb[(bb * NCH + ch) * DIM + h];
#pragma unroll 1
        for (int i0 = MTILE - 8; i0 >= 0; i0 -= 8) {
            float4 a0 = *(const float4*)(d_at + base + i0);
            float4 a1 = *(const float4*)(d_at + base + i0 + 4);
            float4 b0 = *(const float4*)(d_bt + base + i0);
            float4 b1 = *(const float4*)(d_bt + base + i0 + 4);
            float a[8] = {a0.x, a0.y, a0.z, a0.w, a1.x, a1.y, a1.z, a1.w};
            float bv[8] = {b0.x, b0.y, b0.z, b0.w, b1.x, b1.y, b1.z, b1.w};
#pragma unroll
            for (int i = 7; i >= 0; i--) {
                hb = fmaf(a[i], hb, bv[i]);
                B_s[(i0 + i) * WST + h] = tf32r(hb);
            }
        }
    }
    copy_tile(W_s, d_wimg + 3 * TILE_F, tid);
    __syncthreads();

    float acc[16][4];
    zero_acc(acc);
    wgemm(sbF, sbW, acc, rb, cb, lane);
    __syncthreads();
    copy_tile(W_s, d_wimg + 4 * TILE_F, tid);
    __syncthreads();
    wgemm(sbB, sbW, acc, rb, cb, lane);

#pragma unroll
    for (int m = 0; m < 2; m++)
#pragma unroll
        for (int nt = 0; nt < 8; nt++) {
            int row = rb + m * 16 + (lane >> 2);
            int col = cb + nt * 8 + (lane & 3) * 2;
            float* d = acc[m * 8 + nt];
            float2 bo = *(const float2*)(bout + col);
            size_t g0 = (size_t)(t0 + row) * DIM + col;
            size_t g1i = (size_t)(t0 + row + 8) * DIM + col;
            float2 x0 = *(const float2*)(x + g0);
            float2 x1 = *(const float2*)(x + g1i);
            float2 o0, o1;
            o0.x = x0.x + g1 * (d[0] + bo.x);
            o0.y = x0.y + g1 * (d[1] + bo.y);
            o1.x = x1.x + g1 * (d[2] + bo.x);
            o1.y = x1.y + g1 * (d[3] + bo.y);
            *(float2*)(d_x2 + g0) = o0;
            *(float2*)(d_x2 + g1i) = o1;
        }
}

// ---------------- K6: LN -> gelu MLP -> out ----------------
__global__ __launch_bounds__(256) void k6(const float* __restrict__ b1p,
                                          const float* __restrict__ b2p,
                                          float* __restrict__ out) {
    extern __shared__ float sm[];
    float* A_s = sm;
    float* G_s = sm + TILE_F;
    float* W_s = sm + 2 * TILE_F;
    u32 sbA = smem_u32(A_s), sbG = smem_u32(G_s), sbW = smem_u32(W_s);
    int tid = threadIdx.x, lane = tid & 31, wid = tid >> 5;
    int t0 = blockIdx.x * MTILE;
    int bb = t0 / SEQ;
    float alpha = 1.f + d_scal[bb * 6 + 3];
    float bc2 = d_scal[bb * 6 + 4], g2 = d_scal[bb * 6 + 5];
    int rb = (wid >> 1) * 32, cb = (wid & 1) * 64;

#pragma unroll 1
    for (int rep = 0; rep < 16; rep++) {
        int r = wid * 16 + rep;
        float4 v = ((const float4*)(d_x2 + (size_t)(t0 + r) * DIM))[lane];
        float s = warp_sum(v.x + v.y + v.z + v.w);
        float sq = warp_sum(v.x * v.x + v.y * v.y + v.z * v.z + v.w * v.w);
        float m = s * (1.f / 128.f);
        float var = sq * (1.f / 128.f) - m * m;
        float r1 = rsqrtf(var + 1e-6f);
        float4 o;
        o.x = tf32r(alpha * ((v.x - m) * r1) + bc2);
        o.y = tf32r(alpha * ((v.y - m) * r1) + bc2);
        o.z = tf32r(alpha * ((v.z - m) * r1) + bc2);
        o.w = tf32r(alpha * ((v.w - m) * r1) + bc2);
        *(float4*)(A_s + r * WST + 4 * lane) = o;
    }

    float accO[16][4];
    zero_acc(accO);

#pragma unroll 1
    for (int c = 0; c < 4; c++) {
        copy_tile(W_s, d_wimg + (5 + c) * TILE_F, tid);
        __syncthreads();
        float acc[16][4];
        zero_acc(acc);
        wgemm(sbA, sbW, acc, rb, cb, lane);
        __syncthreads();
        // gelu epilogue -> G_s (tanh.approx)
#pragma unroll
        for (int m = 0; m < 2; m++)
#pragma unroll
            for (int nt = 0; nt < 8; nt++) {
                int row = rb + m * 16 + (lane >> 2);
                int col = cb + nt * 8 + (lane & 3) * 2;
                float2 bn = *(const float2*)(b1p + c * 128 + col);
                float* d = acc[m * 8 + nt];
#pragma unroll
                for (int i = 0; i < 4; i++) {
                    int q = i & 1;
                    int r2 = row + (i >> 1) * 8;
                    float hpre = d[i] + (q ? bn.y : bn.x);
                    float t = 0.7978845608028654f * (hpre + 0.044715f * hpre * hpre * hpre);
                    G_s[r2 * WST + col + q] = tf32r(0.5f * hpre * (1.f + tanh_ap(t)));
                }
            }
        copy_tile(W_s, d_wimg + (9 + c) * TILE_F, tid);
        __syncthreads();
        wgemm(sbG, sbW, accO, rb, cb, lane);
        __syncthreads();
    }

#pragma unroll
    for (int m = 0; m < 2; m++)
#pragma unroll
        for (int nt = 0; nt < 8; nt++) {
            int row = rb + m * 16 + (lane >> 2);
            int col = cb + nt * 8 + (lane & 3) * 2;
            float* d = accO[m * 8 + nt];
            float2 bo = *(const float2*)(b2p + col);
            size_t g0 = (size_t)(t0 + row) * DIM + col;
            size_t g1i = (size_t)(t0 + row + 8) * DIM + col;
            float2 x0 = *(const float2*)(d_x2 + g0);
            float2 x1 = *(const float2*)(d_x2 + g1i);
            float2 o0, o1;
            o0.x = x0.x + g2 * (d[0] + bo.x);
            o0.y = x0.y + g2 * (d[1] + bo.y);
            o1.x = x1.x + g2 * (d[2] + bo.x);
            o1.y = x1.y + g2 * (d[3] + bo.y);
            *(float2*)(out + g0) = o0;
            *(float2*)(out + g1i) = o1;
        }
}

// ---------------- host ----------------
extern "C" void kernel_launch(void* const* d_in, const int* in_sizes, int n_in,
                              void* d_out, int out_size) {
    const float* x        = (const float*)d_in[0];
    const float* c        = (const float*)d_in[1];
    const float* cln1_sw  = (const float*)d_in[2];
    const float* cln1_sb  = (const float*)d_in[3];
    const float* cln1_bw  = (const float*)d_in[4];
    const float* cln1_bb  = (const float*)d_in[5];
    const float* gate1_w  = (const float*)d_in[6];
    const float* gate1_b  = (const float*)d_in[7];
    const float* rnn_in_w = (const float*)d_in[8];
    const float* rnn_in_b = (const float*)d_in[9];
    const float* pos_emb  = (const float*)d_in[10];
    const float* rnn_wi   = (const float*)d_in[11];
    const float* rnn_bi   = (const float*)d_in[12];
    const float* rnn_wr   = (const float*)d_in[13];
    const float* rnn_br   = (const float*)d_in[14];
    const float* rnn_a    = (const float*)d_in[15];
    const float* rnn_out_w= (const float*)d_in[16];
    const float* rnn_out_b= (const float*)d_in[17];
    const float* cln2_sw  = (const float*)d_in[18];
    const float* cln2_sb  = (const float*)d_in[19];
    const float* cln2_bw  = (const float*)d_in[20];
    const float* cln2_bb  = (const float*)d_in[21];
    const float* gate2_w  = (const float*)d_in[22];
    const float* gate2_b  = (const float*)d_in[23];
    const float* mlp_w1   = (const float*)d_in[24];
    const float* mlp_b1   = (const float*)d_in[25];
    const float* mlp_w2   = (const float*)d_in[26];
    const float* mlp_b2   = (const float*)d_in[27];
    float* out = (float*)d_out;

    cudaFuncSetAttribute(k1,  cudaFuncAttributeMaxDynamicSharedMemorySize, SMEM_BYTES);
    cudaFuncSetAttribute(k45, cudaFuncAttributeMaxDynamicSharedMemorySize, SMEM_BYTES);
    cudaFuncSetAttribute(k6,  cudaFuncAttributeMaxDynamicSharedMemorySize, SMEM_BYTES);

    k0<<<1, 256>>>(c,
                   cln1_sw, cln1_sb, cln1_bw, cln1_bb, gate1_w, gate1_b,
                   cln2_sw, cln2_sb, cln2_bw, cln2_bb, gate2_w, gate2_b,
                   rnn_a);
    k0w<<<13, 256>>>(rnn_in_w, rnn_wi, rnn_wr, rnn_out_w, mlp_w1, mlp_w2);
    k1<<<NBLK, 256, SMEM_BYTES>>>(x, rnn_in_b, pos_emb, rnn_bi, rnn_br);
    k3<<<BSZ, 256>>>();
    k45<<<NBLK, 256, SMEM_BYTES>>>(x, rnn_out_b);
    k6<<<NBLK, 256, SMEM_BYTES>>>(mlp_b1, mlp_b2, out);
}